// round 13
// baseline (speedup 1.0000x reference)
#include <cuda_runtime.h>
#include <cuda_bf16.h>
#include <cstdint>

// Problem constants
#define SS   128
#define BB   16
#define EE   512
#define HH   512
#define GG   2048
#define VV   32000
#define LNEPS 1e-5f
#define HPAD 514

// ---------------- scratch (device globals; 256B-aligned) ----------------
__device__ __align__(256) float g_xg[SS * BB * GG];     // (s,b,g) gate preacts
__device__ __align__(256) float g_hs[BB * SS * HH];     // hidden states
__device__ __align__(256) float g_hbuf[2][BB * HH];     // ping-pong h broadcast
__device__ __align__(256) unsigned g_cnt8[2048];        // 8 counters, 1KB apart
__device__ unsigned g_master;
__device__ unsigned g_bar_gen;
// bf16 split operands
__device__ __align__(256) __nv_bfloat16 g_nhi[BB * SS * HH];
__device__ __align__(256) __nv_bfloat16 g_nlo[BB * SS * HH];
__device__ __align__(256) __nv_bfloat16 g_whi[VV * HH];
__device__ __align__(256) __nv_bfloat16 g_wlo[VV * HH];
__device__ __align__(256) __nv_bfloat16 g_ahi[SS * BB * EE];
__device__ __align__(256) __nv_bfloat16 g_alo[SS * BB * EE];
__device__ __align__(256) __nv_bfloat16 g_ihhi[GG * EE];
__device__ __align__(256) __nv_bfloat16 g_ihlo[GG * EE];

__device__ __forceinline__ float sigf(float x) { return 1.0f / (1.0f + __expf(-x)); }
__device__ __forceinline__ float tanhfast(float x) { return 2.0f / (1.0f + __expf(-2.0f * x)) - 1.0f; }

__device__ __forceinline__ uint32_t smem_u32(const void* p) {
    uint32_t a;
    asm("{ .reg .u64 t; cvta.to.shared.u64 t, %1; cvt.u32.u64 %0, t; }" : "=r"(a) : "l"(p));
    return a;
}

__device__ __forceinline__ void split_bf16(float v, __nv_bfloat16& h, __nv_bfloat16& l) {
    h = __float2bfloat16_rn(v);
    l = __float2bfloat16_rn(v - __bfloat162float(h));
}

// ============================================================================
// fp32 -> bf16 hi/lo split (grid-stride, float4)
// ============================================================================
__global__ __launch_bounds__(256) void conv_split(
    const float* __restrict__ src, __nv_bfloat16* __restrict__ dhi,
    __nv_bfloat16* __restrict__ dlo, unsigned total4)
{
    const float4* s4 = (const float4*)src;
    for (unsigned p = blockIdx.x * blockDim.x + threadIdx.x; p < total4;
         p += gridDim.x * blockDim.x) {
        float4 v = s4[p];
        __nv_bfloat16 h0, h1, h2, h3, l0, l1, l2, l3;
        split_bf16(v.x, h0, l0); split_bf16(v.y, h1, l1);
        split_bf16(v.z, h2, l2); split_bf16(v.w, h3, l3);
        ((__nv_bfloat162*)dhi)[p * 2 + 0] = __nv_bfloat162(h0, h1);
        ((__nv_bfloat162*)dhi)[p * 2 + 1] = __nv_bfloat162(h2, h3);
        ((__nv_bfloat162*)dlo)[p * 2 + 0] = __nv_bfloat162(l0, l1);
        ((__nv_bfloat162*)dlo)[p * 2 + 1] = __nv_bfloat162(l2, l3);
    }
}

// ============================================================================
// Embedding gather + bf16 hi/lo split. Row m -> token x[(m&15)*SS + (m>>4)].
// ============================================================================
__global__ __launch_bounds__(128) void conv_emb(
    const float* __restrict__ emb, const int* __restrict__ x)
{
    const int m = blockIdx.x;
    const int tid = threadIdx.x;
    const int token = x[(m & 15) * SS + (m >> 4)];
    float4 v = *(const float4*)(emb + (size_t)token * 512 + tid * 4);
    __nv_bfloat16 h0, h1, h2, h3, l0, l1, l2, l3;
    split_bf16(v.x, h0, l0); split_bf16(v.y, h1, l1);
    split_bf16(v.z, h2, l2); split_bf16(v.w, h3, l3);
    ((__nv_bfloat162*)(g_ahi + (size_t)m * 512))[tid * 2 + 0] = __nv_bfloat162(h0, h1);
    ((__nv_bfloat162*)(g_ahi + (size_t)m * 512))[tid * 2 + 1] = __nv_bfloat162(h2, h3);
    ((__nv_bfloat162*)(g_alo + (size_t)m * 512))[tid * 2 + 0] = __nv_bfloat162(l0, l1);
    ((__nv_bfloat162*)(g_alo + (size_t)m * 512))[tid * 2 + 1] = __nv_bfloat162(l2, l3);
}

// ============================================================================
// Persistent LSTM recurrence — R12 version (fused reduce/gate, deferred g_hs)
// ============================================================================
__global__ __launch_bounds__(256, 1) void lstm_kernel(
    const float* __restrict__ Whh,
    const float* __restrict__ z,
    float* __restrict__ out_hc)
{
    extern __shared__ float sm[];
    float* Wsm = sm;
    float* hsm = Wsm + 16 * HPAD;
    float* red = hsm + 16 * HPAD;
    float* cst = red + 4096;

    const int tid = threadIdx.x;
    const int cta = blockIdx.x;

    unsigned gen0 = 0;
    if (tid == 0) gen0 = *((volatile unsigned*)&g_bar_gen);

    for (int i = tid; i < 16 * 128; i += 256) {
        int r = i >> 7;
        int e4 = (i & 127) * 4;
        int grow = (r >> 2) * 512 + cta * 4 + (r & 3);
        float4 w = *(const float4*)(Whh + (size_t)grow * 512 + e4);
        float* dst = &Wsm[r * HPAD + e4];
        dst[0] = w.x; dst[1] = w.y; dst[2] = w.z; dst[3] = w.w;
    }
    for (int i = tid; i < 16 * 128; i += 256) {
        int b = i >> 7;
        int e4 = (i & 127) * 4;
        float4 h = *(const float4*)(z + b * 1024 + e4);
        float* dst = &hsm[b * HPAD + e4];
        dst[0] = h.x; dst[1] = h.y; dst[2] = h.z; dst[3] = h.w;
    }
    if (tid < 64) {
        int ul = tid >> 4, b = tid & 15;
        cst[ul * 16 + b] = z[b * 1024 + 512 + cta * 4 + ul];
    }
    __syncthreads();

    const int kq = tid >> 4;
    const int rq = (tid >> 2) & 3;
    const int bq = tid & 3;
    const int gul = tid >> 4;     // gate-thread unit (tid<64)
    const int gb = tid & 15;      // gate-thread batch

    float hsave = 0.0f;

    for (int t = 0; t < SS; t++) {
        // gate threads prefetch their 4 xg values (i,f,g,o) for this step
        float xg4[4];
        if (tid < 64) {
#pragma unroll
            for (int q = 0; q < 4; q++)
                xg4[q] = __ldg(&g_xg[(size_t)(t * 16 + gb) * 2048 + q * 512 + cta * 4 + gul]);
        }

        float acc00=0,acc01=0,acc02=0,acc03=0;
        float acc10=0,acc11=0,acc12=0,acc13=0;
        float acc20=0,acc21=0,acc22=0,acc23=0;
        float acc30=0,acc31=0,acc32=0,acc33=0;
        const float* h0p = &hsm[(bq * 4 + 0) * HPAD];
        const float* h1p = &hsm[(bq * 4 + 1) * HPAD];
        const float* h2p = &hsm[(bq * 4 + 2) * HPAD];
        const float* h3p = &hsm[(bq * 4 + 3) * HPAD];
        const float* w0p = &Wsm[(rq * 4 + 0) * HPAD];
        const float* w1p = &Wsm[(rq * 4 + 1) * HPAD];
        const float* w2p = &Wsm[(rq * 4 + 2) * HPAD];
        const float* w3p = &Wsm[(rq * 4 + 3) * HPAD];
#pragma unroll 4
        for (int j = 0; j < 16; j++) {
            int e = (kq + 16 * j) * 2;
            float2 hv0 = *(const float2*)(h0p + e);
            float2 hv1 = *(const float2*)(h1p + e);
            float2 hv2 = *(const float2*)(h2p + e);
            float2 hv3 = *(const float2*)(h3p + e);
            float2 wv;
            wv = *(const float2*)(w0p + e);
            acc00 += wv.x*hv0.x + wv.y*hv0.y; acc01 += wv.x*hv1.x + wv.y*hv1.y;
            acc02 += wv.x*hv2.x + wv.y*hv2.y; acc03 += wv.x*hv3.x + wv.y*hv3.y;
            wv = *(const float2*)(w1p + e);
            acc10 += wv.x*hv0.x + wv.y*hv0.y; acc11 += wv.x*hv1.x + wv.y*hv1.y;
            acc12 += wv.x*hv2.x + wv.y*hv2.y; acc13 += wv.x*hv3.x + wv.y*hv3.y;
            wv = *(const float2*)(w2p + e);
            acc20 += wv.x*hv0.x + wv.y*hv0.y; acc21 += wv.x*hv1.x + wv.y*hv1.y;
            acc22 += wv.x*hv2.x + wv.y*hv2.y; acc23 += wv.x*hv3.x + wv.y*hv3.y;
            wv = *(const float2*)(w3p + e);
            acc30 += wv.x*hv0.x + wv.y*hv0.y; acc31 += wv.x*hv1.x + wv.y*hv1.y;
            acc32 += wv.x*hv2.x + wv.y*hv2.y; acc33 += wv.x*hv3.x + wv.y*hv3.y;
        }
        {
            float* rbase = &red[kq * 256];
            int r0 = rq * 4, b0 = bq * 4;
            rbase[(r0+0)*16 + b0+0]=acc00; rbase[(r0+0)*16 + b0+1]=acc01; rbase[(r0+0)*16 + b0+2]=acc02; rbase[(r0+0)*16 + b0+3]=acc03;
            rbase[(r0+1)*16 + b0+0]=acc10; rbase[(r0+1)*16 + b0+1]=acc11; rbase[(r0+1)*16 + b0+2]=acc12; rbase[(r0+1)*16 + b0+3]=acc13;
            rbase[(r0+2)*16 + b0+0]=acc20; rbase[(r0+2)*16 + b0+1]=acc21; rbase[(r0+2)*16 + b0+2]=acc22; rbase[(r0+2)*16 + b0+3]=acc23;
            rbase[(r0+3)*16 + b0+0]=acc30; rbase[(r0+3)*16 + b0+1]=acc31; rbase[(r0+3)*16 + b0+2]=acc32; rbase[(r0+3)*16 + b0+3]=acc33;
        }
        __syncthreads();

        // ---- fused reduce + gate combine: 64 threads ----
        if (tid < 64) {
            float g4[4];
#pragma unroll
            for (int q = 0; q < 4; q++) {
                int r = q * 4 + gul;
                float s = 0.0f;
#pragma unroll
                for (int k2 = 0; k2 < 16; k2++) s += red[k2 * 256 + r * 16 + gb];
                g4[q] = s + xg4[q];
            }
            float c = cst[gul * 16 + gb];
            c = sigf(g4[1]) * c + sigf(g4[0]) * tanhfast(g4[2]);
            float hN = sigf(g4[3]) * tanhfast(c);
            cst[gul * 16 + gb] = c;
            int ug = cta * 4 + gul;
            g_hbuf[t & 1][gb * 512 + ug] = hN;
            hsave = hN;
            if (t == SS - 1) {
                g_hs[(size_t)gb * (SS * HH) + t * 512 + ug] = hN;
                out_hc[gb * 1024 + ug] = hN;
                out_hc[gb * 1024 + 512 + ug] = c;
            }
        }

        if (t < SS - 1) {
            __threadfence();
            __syncthreads();
            if (tid == 0) {
                unsigned target = gen0 + (unsigned)t + 1u;
                unsigned a = atomicAdd(&g_cnt8[(cta & 7) << 8], 1u);
                if (a == 15u) {
                    unsigned m = atomicAdd(&g_master, 1u);
                    if (m == 7u) {
#pragma unroll
                        for (int q = 0; q < 8; q++)
                            atomicExch(&g_cnt8[q << 8], 0u);
                        atomicExch(&g_master, 0u);
                        __threadfence();
                        atomicAdd(&g_bar_gen, 1u);
                    }
                }
                while ((int)(*((volatile unsigned*)&g_bar_gen) - target) < 0) { }
            }
            __syncthreads();
            // deferred g_hs store (off the release critical path)
            if (tid < 64) {
                int ug = cta * 4 + gul;
                g_hs[(size_t)gb * (SS * HH) + t * 512 + ug] = hsave;
            }
            // reload h broadcast (bypass L1)
            const float2* src = (const float2*)(&g_hbuf[t & 1][0]);
            for (int i = tid; i < 4096; i += 256) {
                int b = i >> 8;
                int e2 = i & 255;
                float2 v = __ldcg(src + i);
                *(float2*)&hsm[b * HPAD + e2 * 2] = v;
            }
            __syncthreads();
        }
    }
}

// ============================================================================
// LayerNorm -> bf16 hi/lo split outputs
// ============================================================================
__global__ __launch_bounds__(128) void ln_kernel(
    const float* __restrict__ gamma, const float* __restrict__ beta)
{
    __shared__ float rs[4], rs2[4];
    const int m = blockIdx.x;
    const int tid = threadIdx.x;
    const float* row = g_hs + (size_t)m * 512;

    float4 v = *(const float4*)(row + tid * 4);
    float s  = v.x + v.y + v.z + v.w;
    float s2 = v.x * v.x + v.y * v.y + v.z * v.z + v.w * v.w;

    const int lane = tid & 31, w = tid >> 5;
#pragma unroll
    for (int o = 16; o; o >>= 1) {
        s  += __shfl_xor_sync(0xffffffffu, s, o);
        s2 += __shfl_xor_sync(0xffffffffu, s2, o);
    }
    if (lane == 0) { rs[w] = s; rs2[w] = s2; }
    __syncthreads();
    s  = rs[0] + rs[1] + rs[2] + rs[3];
    s2 = rs2[0] + rs2[1] + rs2[2] + rs2[3];

    float mu = s * (1.0f / 512.0f);
    float var = s2 * (1.0f / 512.0f) - mu * mu;
    float inv = rsqrtf(var + LNEPS);

    float4 g4 = *(const float4*)(gamma + tid * 4);
    float4 b4 = *(const float4*)(beta + tid * 4);
    float o0 = (v.x - mu) * inv * g4.x + b4.x;
    float o1 = (v.y - mu) * inv * g4.y + b4.y;
    float o2 = (v.z - mu) * inv * g4.z + b4.z;
    float o3 = (v.w - mu) * inv * g4.w + b4.w;

    __nv_bfloat16 h0, h1, h2, h3, l0, l1, l2, l3;
    split_bf16(o0, h0, l0); split_bf16(o1, h1, l1);
    split_bf16(o2, h2, l2); split_bf16(o3, h3, l3);

    __nv_bfloat162* hp = (__nv_bfloat162*)(g_nhi + (size_t)m * 512);
    __nv_bfloat162* lp = (__nv_bfloat162*)(g_nlo + (size_t)m * 512);
    hp[tid * 2 + 0] = __nv_bfloat162(h0, h1);
    hp[tid * 2 + 1] = __nv_bfloat162(h2, h3);
    lp[tid * 2 + 0] = __nv_bfloat162(l0, l1);
    lp[tid * 2 + 1] = __nv_bfloat162(l2, l3);
}

// ============================================================================
// mma.sync bf16-split GEMM — exact R9 config (measured best: 40.16us K1)
// CTA tile 128x256, warp tile 64x64, K=512 in 16 chunks of 32, 3-stage cp.async.
// ============================================================================
#define GS_STAGE 49152
#define FC_NCHUNK 16

__device__ __forceinline__ void ldsm_x4(uint32_t& r0, uint32_t& r1, uint32_t& r2,
                                        uint32_t& r3, uint32_t addr) {
    asm volatile("ldmatrix.sync.aligned.m8n8.x4.shared.b16 {%0,%1,%2,%3}, [%4];"
                 : "=r"(r0), "=r"(r1), "=r"(r2), "=r"(r3) : "r"(addr));
}

__device__ __forceinline__ void mma_bf16(float* c, const uint32_t* a, const uint32_t* b) {
    asm volatile(
        "mma.sync.aligned.m16n8k16.row.col.f32.bf16.bf16.f32 "
        "{%0,%1,%2,%3}, {%4,%5,%6,%7}, {%8,%9}, {%0,%1,%2,%3};"
        : "+f"(c[0]), "+f"(c[1]), "+f"(c[2]), "+f"(c[3])
        : "r"(a[0]), "r"(a[1]), "r"(a[2]), "r"(a[3]), "r"(b[0]), "r"(b[1]));
}

__global__ __launch_bounds__(256, 1) void gemm_mma(
    const __nv_bfloat16* __restrict__ Ahi, const __nv_bfloat16* __restrict__ Alo,
    const __nv_bfloat16* __restrict__ Bhi, const __nv_bfloat16* __restrict__ Blo,
    const float* __restrict__ bias0, const float* __restrict__ bias1,
    float* __restrict__ C, int N)
{
    extern __shared__ char smem[];
    const uint32_t sb = smem_u32(smem);
    const int tid = threadIdx.x;
    const int wid = tid >> 5;
    const int lane = tid & 31;
    const int m0 = blockIdx.x * 128;
    const int n0 = blockIdx.y * 256;
    const int warp_m = wid >> 2;   // 0..1 (64 m each)
    const int warp_n = wid & 3;    // 0..3 (64 n each)

    auto load_chunk = [&](int c) {
        const int k0 = c * 32;
        const uint32_t st = sb + (uint32_t)(c % 3) * GS_STAGE;
#pragma unroll
        for (int it = 0; it < 12; it++) {
            int i = it * 256 + tid;
            if (i < 1024) {
                int row = i >> 3;
                int g = i & 7;
                int part = g >> 2;
                int kg = g & 3;
                const __nv_bfloat16* src =
                    (part ? Alo : Ahi) + (size_t)(m0 + row) * 512 + k0 + kg * 8;
                uint32_t dst = st + (uint32_t)(row * 128) +
                               ((uint32_t)(g ^ (row & 7)) << 4);
                asm volatile("cp.async.cg.shared.global [%0], [%1], 16;" :: "r"(dst), "l"(src));
            } else {
                int li = i - 1024;
                int row = li >> 3;
                int g = li & 7;
                int part = g >> 2;
                int kg = g & 3;
                const __nv_bfloat16* src =
                    (part ? Blo : Bhi) + (size_t)(n0 + row) * 512 + k0 + kg * 8;
                uint32_t dst = st + 16384u + (uint32_t)(row * 128) +
                               ((uint32_t)(g ^ (row & 7)) << 4);
                asm volatile("cp.async.cg.shared.global [%0], [%1], 16;" :: "r"(dst), "l"(src));
            }
        }
        asm volatile("cp.async.commit_group;" ::: "memory");
    };

    load_chunk(0);
    load_chunk(1);

    const int t = lane >> 3, trow = lane & 7;
    const int a_mpart = (t & 1) * 8 + trow;
    const int a_gsel = t >> 1;
    uint32_t a_row_off[4]; uint32_t a_sw[4];
#pragma unroll
    for (int mf = 0; mf < 4; mf++) {
        int ml = warp_m * 64 + mf * 16 + a_mpart;
        a_row_off[mf] = (uint32_t)(ml * 128);
        a_sw[mf] = (uint32_t)(ml & 7);
    }
    const int b_fragsel = t >> 1;
    const int b_gsel = t & 1;
    uint32_t b_row_off[4]; uint32_t b_sw[4];
#pragma unroll
    for (int nf2 = 0; nf2 < 4; nf2++) {
        int nl = warp_n * 64 + (nf2 * 2 + b_fragsel) * 8 + trow;
        b_row_off[nf2] = (uint32_t)(nl * 128) + 16384u;
        b_sw[nf2] = (uint32_t)(nl & 7);
    }

    float acc[4][8][4];
#pragma unroll
    for (int i = 0; i < 4; i++)
#pragma unroll
        for (int j = 0; j < 8; j++)
#pragma unroll
            for (int r = 0; r < 4; r++) acc[i][j][r] = 0.0f;

    for (int c = 0; c < FC_NCHUNK; c++) {
        if (c < FC_NCHUNK - 1)
            asm volatile("cp.async.wait_group 1;" ::: "memory");
        else
            asm volatile("cp.async.wait_group 0;" ::: "memory");
        __syncthreads();
        if (c + 2 < FC_NCHUNK) load_chunk(c + 2);

        const uint32_t st = sb + (uint32_t)(c % 3) * GS_STAGE;
#pragma unroll
        for (int ks = 0; ks < 2; ks++) {
            uint32_t ah[4][4], al[4][4];
#pragma unroll
            for (int mf = 0; mf < 4; mf++) {
                uint32_t Ghi = (uint32_t)(ks * 2 + a_gsel);
                uint32_t Glo = Ghi + 4u;
                ldsm_x4(ah[mf][0], ah[mf][1], ah[mf][2], ah[mf][3],
                        st + a_row_off[mf] + ((Ghi ^ a_sw[mf]) << 4));
                ldsm_x4(al[mf][0], al[mf][1], al[mf][2], al[mf][3],
                        st + a_row_off[mf] + ((Glo ^ a_sw[mf]) << 4));
            }
#pragma unroll
            for (int nf2 = 0; nf2 < 4; nf2++) {
                uint32_t bh[2][2], bl[2][2];
                uint32_t Ghi = (uint32_t)(ks * 2 + b_gsel);
                uint32_t Glo = Ghi + 4u;
                ldsm_x4(bh[0][0], bh[0][1], bh[1][0], bh[1][1],
                        st + b_row_off[nf2] + ((Ghi ^ b_sw[nf2]) << 4));
                ldsm_x4(bl[0][0], bl[0][1], bl[1][0], bl[1][1],
                        st + b_row_off[nf2] + ((Glo ^ b_sw[nf2]) << 4));
#pragma unroll
                for (int mf = 0; mf < 4; mf++)
#pragma unroll
                    for (int j = 0; j < 2; j++)
                        mma_bf16(acc[mf][nf2 * 2 + j], ah[mf], bh[j]);   // hi*hi
#pragma unroll
                for (int mf = 0; mf < 4; mf++)
#pragma unroll
                    for (int j = 0; j < 2; j++)
                        mma_bf16(acc[mf][nf2 * 2 + j], al[mf], bh[j]);   // lo*hi
#pragma unroll
                for (int mf = 0; mf < 4; mf++)
#pragma unroll
                    for (int j = 0; j < 2; j++)
                        mma_bf16(acc[mf][nf2 * 2 + j], ah[mf], bl[j]);   // hi*lo
            }
        }
    }

    // ---- epilogue: direct global stores with bias ----
    const int lrow = lane >> 2;
    const int lcol = (lane & 3) * 2;
#pragma unroll
    for (int mf = 0; mf < 4; mf++) {
        int r0 = m0 + warp_m * 64 + mf * 16 + lrow;
        float* crow0 = C + (size_t)r0 * N;
        float* crow1 = crow0 + (size_t)8 * N;
#pragma unroll
        for (int nf = 0; nf < 8; nf++) {
            int cn = n0 + warp_n * 64 + nf * 8 + lcol;
            float b0 = __ldg(bias0 + cn);
            float b1 = __ldg(bias0 + cn + 1);
            if (bias1) { b0 += __ldg(bias1 + cn); b1 += __ldg(bias1 + cn + 1); }
            float2 v0 = { acc[mf][nf][0] + b0, acc[mf][nf][1] + b1 };
            float2 v1 = { acc[mf][nf][2] + b0, acc[mf][nf][3] + b1 };
            *(float2*)(crow0 + cn) = v0;
            *(float2*)(crow1 + cn) = v1;
        }
    }
}

// ============================================================================
// launch
// ============================================================================
extern "C" void kernel_launch(void* const* d_in, const int* in_sizes, int n_in,
                              void* d_out, int out_size)
{
    const int*   x    = (const int*)d_in[0];
    const float* z    = (const float*)d_in[1];
    const float* emb  = (const float*)d_in[2];
    const float* W_ih = (const float*)d_in[3];
    const float* W_hh = (const float*)d_in[4];
    const float* b_ih = (const float*)d_in[5];
    const float* b_hh = (const float*)d_in[6];
    const float* ln_g = (const float*)d_in[7];
    const float* ln_b = (const float*)d_in[8];
    const float* fc_W = (const float*)d_in[9];
    const float* fc_b = (const float*)d_in[10];
    float* out = (float*)d_out;

    float* xg_p;
    __nv_bfloat16 *whi_p, *wlo_p, *ahi_p, *alo_p, *ihhi_p, *ihlo_p, *nhi_p, *nlo_p;
    cudaGetSymbolAddress((void**)&xg_p, g_xg);
    cudaGetSymbolAddress((void**)&whi_p, g_whi);
    cudaGetSymbolAddress((void**)&wlo_p, g_wlo);
    cudaGetSymbolAddress((void**)&ahi_p, g_ahi);
    cudaGetSymbolAddress((void**)&alo_p, g_alo);
    cudaGetSymbolAddress((void**)&ihhi_p, g_ihhi);
    cudaGetSymbolAddress((void**)&ihlo_p, g_ihlo);
    cudaGetSymbolAddress((void**)&nhi_p, g_nhi);
    cudaGetSymbolAddress((void**)&nlo_p, g_nlo);

    const int gemm_smem = 3 * GS_STAGE;   // 147456
    cudaFuncSetAttribute(gemm_mma, cudaFuncAttributeMaxDynamicSharedMemorySize, gemm_smem);

    // K0a: fc_W -> bf16 hi/lo
    conv_split<<<2048, 256>>>(fc_W, whi_p, wlo_p, (unsigned)(VV * HH / 4));
    // K0b: W_ih -> bf16 hi/lo
    conv_split<<<256, 256>>>(W_ih, ihhi_p, ihlo_p, (unsigned)(GG * EE / 4));
    // K0c: gathered embedding -> bf16 hi/lo
    conv_emb<<<SS * BB, 128>>>(emb, x);

    // K1: input-side gate GEMM on tensor cores -> g_xg
    {
        dim3 grid((SS * BB) / 128, GG / 256);  // (16, 8)
        gemm_mma<<<grid, 256, gemm_smem>>>(ahi_p, alo_p, ihhi_p, ihlo_p,
                                           b_ih, b_hh, xg_p, GG);
    }

    // K2: persistent LSTM recurrence
    {
        const int smem = (16 * HPAD * 2 + 4096 + 64) * 4;
        cudaFuncSetAttribute(lstm_kernel, cudaFuncAttributeMaxDynamicSharedMemorySize, smem);
        lstm_kernel<<<128, 256, smem>>>(W_hh, z, out + (size_t)BB * SS * VV);
    }

    // K3: layernorm -> bf16 hi/lo
    ln_kernel<<<BB * SS, 128>>>(ln_g, ln_b);

    // K4: FC logits GEMM on tensor cores
    {
        dim3 grid((SS * BB) / 128, VV / 256);  // (16, 125)
        gemm_mma<<<grid, 256, gemm_smem>>>(nhi_p, nlo_p, whi_p, wlo_p,
                                           fc_b, nullptr, out, VV);
    }
}

// round 14
// speedup vs baseline: 1.1295x; 1.1295x over previous
#include <cuda_runtime.h>
#include <cuda_bf16.h>
#include <cuda_fp16.h>
#include <cstdint>

// Problem constants
#define SS   128
#define BB   16
#define EE   512
#define HH   512
#define GG   2048
#define VV   32000
#define LNEPS 1e-5f
#define HPAD 514

// ---------------- scratch (device globals; 256B-aligned) ----------------
__device__ __align__(256) float g_xg[SS * BB * GG];     // (s,b,g) gate preacts
__device__ __align__(256) float g_hs[BB * SS * HH];     // hidden states
__device__ __align__(256) float g_hbuf[2][BB * HH];     // ping-pong h broadcast
__device__ __align__(256) unsigned g_cnt8[2048];        // 8 counters, 1KB apart
__device__ unsigned g_master;
__device__ unsigned g_bar_gen;
// bf16 split operands (K1 path — proven)
__device__ __align__(256) __nv_bfloat16 g_ahi[SS * BB * EE];
__device__ __align__(256) __nv_bfloat16 g_alo[SS * BB * EE];
__device__ __align__(256) __nv_bfloat16 g_ihhi[GG * EE];
__device__ __align__(256) __nv_bfloat16 g_ihlo[GG * EE];
// fp16 operands (K4 path — 2-term)
__device__ __align__(256) __half g_n16[BB * SS * HH];   // LN out, single fp16
__device__ __align__(256) __half g_w16hi[VV * HH];      // fc_W fp16 hi
__device__ __align__(256) __half g_w16lo[VV * HH];      // fc_W fp16 lo

__device__ __forceinline__ float sigf(float x) { return 1.0f / (1.0f + __expf(-x)); }
__device__ __forceinline__ float tanhfast(float x) { return 2.0f / (1.0f + __expf(-2.0f * x)) - 1.0f; }

__device__ __forceinline__ uint32_t smem_u32(const void* p) {
    uint32_t a;
    asm("{ .reg .u64 t; cvta.to.shared.u64 t, %1; cvt.u32.u64 %0, t; }" : "=r"(a) : "l"(p));
    return a;
}

__device__ __forceinline__ void split_bf16(float v, __nv_bfloat16& h, __nv_bfloat16& l) {
    h = __float2bfloat16_rn(v);
    l = __float2bfloat16_rn(v - __bfloat162float(h));
}

// ============================================================================
// fp32 -> bf16 hi/lo split (grid-stride, float4) — K1 operands
// ============================================================================
__global__ __launch_bounds__(256) void conv_split(
    const float* __restrict__ src, __nv_bfloat16* __restrict__ dhi,
    __nv_bfloat16* __restrict__ dlo, unsigned total4)
{
    const float4* s4 = (const float4*)src;
    for (unsigned p = blockIdx.x * blockDim.x + threadIdx.x; p < total4;
         p += gridDim.x * blockDim.x) {
        float4 v = s4[p];
        __nv_bfloat16 h0, h1, h2, h3, l0, l1, l2, l3;
        split_bf16(v.x, h0, l0); split_bf16(v.y, h1, l1);
        split_bf16(v.z, h2, l2); split_bf16(v.w, h3, l3);
        ((__nv_bfloat162*)dhi)[p * 2 + 0] = __nv_bfloat162(h0, h1);
        ((__nv_bfloat162*)dhi)[p * 2 + 1] = __nv_bfloat162(h2, h3);
        ((__nv_bfloat162*)dlo)[p * 2 + 0] = __nv_bfloat162(l0, l1);
        ((__nv_bfloat162*)dlo)[p * 2 + 1] = __nv_bfloat162(l2, l3);
    }
}

// ============================================================================
// fp32 -> fp16 hi/lo split (grid-stride, float4) — K4 weights
// ============================================================================
__global__ __launch_bounds__(256) void conv_split_h(
    const float* __restrict__ src, __half* __restrict__ dhi,
    __half* __restrict__ dlo, unsigned total4)
{
    const float4* s4 = (const float4*)src;
    for (unsigned p = blockIdx.x * blockDim.x + threadIdx.x; p < total4;
         p += gridDim.x * blockDim.x) {
        float4 v = s4[p];
        __half h0 = __float2half_rn(v.x);
        __half h1 = __float2half_rn(v.y);
        __half h2 = __float2half_rn(v.z);
        __half h3 = __float2half_rn(v.w);
        __half l0 = __float2half_rn(v.x - __half2float(h0));
        __half l1 = __float2half_rn(v.y - __half2float(h1));
        __half l2 = __float2half_rn(v.z - __half2float(h2));
        __half l3 = __float2half_rn(v.w - __half2float(h3));
        ((__half2*)dhi)[p * 2 + 0] = __half2(h0, h1);
        ((__half2*)dhi)[p * 2 + 1] = __half2(h2, h3);
        ((__half2*)dlo)[p * 2 + 0] = __half2(l0, l1);
        ((__half2*)dlo)[p * 2 + 1] = __half2(l2, l3);
    }
}

// ============================================================================
// Embedding gather + bf16 hi/lo split. Row m -> token x[(m&15)*SS + (m>>4)].
// ============================================================================
__global__ __launch_bounds__(128) void conv_emb(
    const float* __restrict__ emb, const int* __restrict__ x)
{
    const int m = blockIdx.x;
    const int tid = threadIdx.x;
    const int token = x[(m & 15) * SS + (m >> 4)];
    float4 v = *(const float4*)(emb + (size_t)token * 512 + tid * 4);
    __nv_bfloat16 h0, h1, h2, h3, l0, l1, l2, l3;
    split_bf16(v.x, h0, l0); split_bf16(v.y, h1, l1);
    split_bf16(v.z, h2, l2); split_bf16(v.w, h3, l3);
    ((__nv_bfloat162*)(g_ahi + (size_t)m * 512))[tid * 2 + 0] = __nv_bfloat162(h0, h1);
    ((__nv_bfloat162*)(g_ahi + (size_t)m * 512))[tid * 2 + 1] = __nv_bfloat162(h2, h3);
    ((__nv_bfloat162*)(g_alo + (size_t)m * 512))[tid * 2 + 0] = __nv_bfloat162(l0, l1);
    ((__nv_bfloat162*)(g_alo + (size_t)m * 512))[tid * 2 + 1] = __nv_bfloat162(l2, l3);
}

// ============================================================================
// Persistent LSTM recurrence — exact R9 version (best measured)
// ============================================================================
__global__ __launch_bounds__(256, 1) void lstm_kernel(
    const float* __restrict__ Whh,
    const float* __restrict__ z,
    float* __restrict__ out_hc)
{
    extern __shared__ float sm[];
    float* Wsm = sm;
    float* hsm = Wsm + 16 * HPAD;
    float* red = hsm + 16 * HPAD;
    float* pre = red + 4096;
    float* cst = pre + 256;

    const int tid = threadIdx.x;
    const int cta = blockIdx.x;

    unsigned gen0 = 0;
    if (tid == 0) gen0 = *((volatile unsigned*)&g_bar_gen);

    for (int i = tid; i < 16 * 128; i += 256) {
        int r = i >> 7;
        int e4 = (i & 127) * 4;
        int grow = (r >> 2) * 512 + cta * 4 + (r & 3);
        float4 w = *(const float4*)(Whh + (size_t)grow * 512 + e4);
        float* dst = &Wsm[r * HPAD + e4];
        dst[0] = w.x; dst[1] = w.y; dst[2] = w.z; dst[3] = w.w;
    }
    for (int i = tid; i < 16 * 128; i += 256) {
        int b = i >> 7;
        int e4 = (i & 127) * 4;
        float4 h = *(const float4*)(z + b * 1024 + e4);
        float* dst = &hsm[b * HPAD + e4];
        dst[0] = h.x; dst[1] = h.y; dst[2] = h.z; dst[3] = h.w;
    }
    if (tid < 64) {
        int ul = tid >> 4, b = tid & 15;
        cst[ul * 16 + b] = z[b * 1024 + 512 + cta * 4 + ul];
    }
    __syncthreads();

    const int kq = tid >> 4;
    const int rq = (tid >> 2) & 3;
    const int bq = tid & 3;
    const int xr = tid >> 4, xb = tid & 15;
    const float* xg_addr = &g_xg[(size_t)xb * 2048 + (xr >> 2) * 512 + cta * 4 + (xr & 3)];

    for (int t = 0; t < SS; t++) {
        float xg_v = __ldg(xg_addr + (size_t)t * 16 * 2048);

        float acc00=0,acc01=0,acc02=0,acc03=0;
        float acc10=0,acc11=0,acc12=0,acc13=0;
        float acc20=0,acc21=0,acc22=0,acc23=0;
        float acc30=0,acc31=0,acc32=0,acc33=0;
        const float* h0p = &hsm[(bq * 4 + 0) * HPAD];
        const float* h1p = &hsm[(bq * 4 + 1) * HPAD];
        const float* h2p = &hsm[(bq * 4 + 2) * HPAD];
        const float* h3p = &hsm[(bq * 4 + 3) * HPAD];
        const float* w0p = &Wsm[(rq * 4 + 0) * HPAD];
        const float* w1p = &Wsm[(rq * 4 + 1) * HPAD];
        const float* w2p = &Wsm[(rq * 4 + 2) * HPAD];
        const float* w3p = &Wsm[(rq * 4 + 3) * HPAD];
#pragma unroll 4
        for (int j = 0; j < 16; j++) {
            int e = (kq + 16 * j) * 2;
            float2 hv0 = *(const float2*)(h0p + e);
            float2 hv1 = *(const float2*)(h1p + e);
            float2 hv2 = *(const float2*)(h2p + e);
            float2 hv3 = *(const float2*)(h3p + e);
            float2 wv;
            wv = *(const float2*)(w0p + e);
            acc00 += wv.x*hv0.x + wv.y*hv0.y; acc01 += wv.x*hv1.x + wv.y*hv1.y;
            acc02 += wv.x*hv2.x + wv.y*hv2.y; acc03 += wv.x*hv3.x + wv.y*hv3.y;
            wv = *(const float2*)(w1p + e);
            acc10 += wv.x*hv0.x + wv.y*hv0.y; acc11 += wv.x*hv1.x + wv.y*hv1.y;
            acc12 += wv.x*hv2.x + wv.y*hv2.y; acc13 += wv.x*hv3.x + wv.y*hv3.y;
            wv = *(const float2*)(w2p + e);
            acc20 += wv.x*hv0.x + wv.y*hv0.y; acc21 += wv.x*hv1.x + wv.y*hv1.y;
            acc22 += wv.x*hv2.x + wv.y*hv2.y; acc23 += wv.x*hv3.x + wv.y*hv3.y;
            wv = *(const float2*)(w3p + e);
            acc30 += wv.x*hv0.x + wv.y*hv0.y; acc31 += wv.x*hv1.x + wv.y*hv1.y;
            acc32 += wv.x*hv2.x + wv.y*hv2.y; acc33 += wv.x*hv3.x + wv.y*hv3.y;
        }
        {
            float* rbase = &red[kq * 256];
            int r0 = rq * 4, b0 = bq * 4;
            rbase[(r0+0)*16 + b0+0]=acc00; rbase[(r0+0)*16 + b0+1]=acc01; rbase[(r0+0)*16 + b0+2]=acc02; rbase[(r0+0)*16 + b0+3]=acc03;
            rbase[(r0+1)*16 + b0+0]=acc10; rbase[(r0+1)*16 + b0+1]=acc11; rbase[(r0+1)*16 + b0+2]=acc12; rbase[(r0+1)*16 + b0+3]=acc13;
            rbase[(r0+2)*16 + b0+0]=acc20; rbase[(r0+2)*16 + b0+1]=acc21; rbase[(r0+2)*16 + b0+2]=acc22; rbase[(r0+2)*16 + b0+3]=acc23;
            rbase[(r0+3)*16 + b0+0]=acc30; rbase[(r0+3)*16 + b0+1]=acc31; rbase[(r0+3)*16 + b0+2]=acc32; rbase[(r0+3)*16 + b0+3]=acc33;
        }
        __syncthreads();

        {
            float s = 0.0f;
#pragma unroll
            for (int k2 = 0; k2 < 16; k2++) s += red[k2 * 256 + xr * 16 + xb];
            pre[xr * 16 + xb] = s + xg_v;
        }
        __syncthreads();

        if (tid < 64) {
            int ul = tid >> 4, b = tid & 15;
            int ug = cta * 4 + ul;
            float iv = pre[(0  + ul) * 16 + b];
            float fv = pre[(4  + ul) * 16 + b];
            float gv = pre[(8  + ul) * 16 + b];
            float ov = pre[(12 + ul) * 16 + b];
            float c = cst[ul * 16 + b];
            c = sigf(fv) * c + sigf(iv) * tanhfast(gv);
            float hN = sigf(ov) * tanhfast(c);
            cst[ul * 16 + b] = c;
            g_hbuf[t & 1][b * 512 + ug] = hN;
            g_hs[(size_t)b * (SS * HH) + t * 512 + ug] = hN;
            if (t == SS - 1) {
                out_hc[b * 1024 + ug] = hN;
                out_hc[b * 1024 + 512 + ug] = c;
            }
        }

        if (t < SS - 1) {
            __threadfence();
            __syncthreads();
            if (tid == 0) {
                unsigned target = gen0 + (unsigned)t + 1u;
                unsigned a = atomicAdd(&g_cnt8[(cta & 7) << 8], 1u);
                if (a == 15u) {
                    unsigned m = atomicAdd(&g_master, 1u);
                    if (m == 7u) {
#pragma unroll
                        for (int q = 0; q < 8; q++)
                            atomicExch(&g_cnt8[q << 8], 0u);
                        atomicExch(&g_master, 0u);
                        __threadfence();
                        atomicAdd(&g_bar_gen, 1u);
                    }
                }
                while ((int)(*((volatile unsigned*)&g_bar_gen) - target) < 0) { }
            }
            __syncthreads();
            const float2* src = (const float2*)(&g_hbuf[t & 1][0]);
            for (int i = tid; i < 4096; i += 256) {
                int b = i >> 8;
                int e2 = i & 255;
                float2 v = __ldcg(src + i);
                *(float2*)&hsm[b * HPAD + e2 * 2] = v;
            }
            __syncthreads();
        }
    }
}

// ============================================================================
// LayerNorm -> single fp16 output (feeds the 2-term K4)
// ============================================================================
__global__ __launch_bounds__(128) void ln_kernel(
    const float* __restrict__ gamma, const float* __restrict__ beta)
{
    __shared__ float rs[4], rs2[4];
    const int m = blockIdx.x;
    const int tid = threadIdx.x;
    const float* row = g_hs + (size_t)m * 512;

    float4 v = *(const float4*)(row + tid * 4);
    float s  = v.x + v.y + v.z + v.w;
    float s2 = v.x * v.x + v.y * v.y + v.z * v.z + v.w * v.w;

    const int lane = tid & 31, w = tid >> 5;
#pragma unroll
    for (int o = 16; o; o >>= 1) {
        s  += __shfl_xor_sync(0xffffffffu, s, o);
        s2 += __shfl_xor_sync(0xffffffffu, s2, o);
    }
    if (lane == 0) { rs[w] = s; rs2[w] = s2; }
    __syncthreads();
    s  = rs[0] + rs[1] + rs[2] + rs[3];
    s2 = rs2[0] + rs2[1] + rs2[2] + rs2[3];

    float mu = s * (1.0f / 512.0f);
    float var = s2 * (1.0f / 512.0f) - mu * mu;
    float inv = rsqrtf(var + LNEPS);

    float4 g4 = *(const float4*)(gamma + tid * 4);
    float4 b4 = *(const float4*)(beta + tid * 4);
    float o0 = (v.x - mu) * inv * g4.x + b4.x;
    float o1 = (v.y - mu) * inv * g4.y + b4.y;
    float o2 = (v.z - mu) * inv * g4.z + b4.z;
    float o3 = (v.w - mu) * inv * g4.w + b4.w;

    __half2* np = (__half2*)(g_n16 + (size_t)m * 512);
    np[tid * 2 + 0] = __half2(__float2half_rn(o0), __float2half_rn(o1));
    np[tid * 2 + 1] = __half2(__float2half_rn(o2), __float2half_rn(o3));
}

// ============================================================================
// Shared GEMM helpers
// ============================================================================
#define GS_STAGE 49152
#define FC_NCHUNK 16

__device__ __forceinline__ void ldsm_x4(uint32_t& r0, uint32_t& r1, uint32_t& r2,
                                        uint32_t& r3, uint32_t addr) {
    asm volatile("ldmatrix.sync.aligned.m8n8.x4.shared.b16 {%0,%1,%2,%3}, [%4];"
                 : "=r"(r0), "=r"(r1), "=r"(r2), "=r"(r3) : "r"(addr));
}

__device__ __forceinline__ void mma_bf16(float* c, const uint32_t* a, const uint32_t* b) {
    asm volatile(
        "mma.sync.aligned.m16n8k16.row.col.f32.bf16.bf16.f32 "
        "{%0,%1,%2,%3}, {%4,%5,%6,%7}, {%8,%9}, {%0,%1,%2,%3};"
        : "+f"(c[0]), "+f"(c[1]), "+f"(c[2]), "+f"(c[3])
        : "r"(a[0]), "r"(a[1]), "r"(a[2]), "r"(a[3]), "r"(b[0]), "r"(b[1]));
}

__device__ __forceinline__ void mma_f16(float* c, const uint32_t* a, const uint32_t* b) {
    asm volatile(
        "mma.sync.aligned.m16n8k16.row.col.f32.f16.f16.f32 "
        "{%0,%1,%2,%3}, {%4,%5,%6,%7}, {%8,%9}, {%0,%1,%2,%3};"
        : "+f"(c[0]), "+f"(c[1]), "+f"(c[2]), "+f"(c[3])
        : "r"(a[0]), "r"(a[1]), "r"(a[2]), "r"(a[3]), "r"(b[0]), "r"(b[1]));
}

// ============================================================================
// K1: bf16 3-term GEMM — exact R9 config (proven). C = A@B^T + bias0 + bias1
// ============================================================================
__global__ __launch_bounds__(256, 1) void gemm_mma(
    const __nv_bfloat16* __restrict__ Ahi, const __nv_bfloat16* __restrict__ Alo,
    const __nv_bfloat16* __restrict__ Bhi, const __nv_bfloat16* __restrict__ Blo,
    const float* __restrict__ bias0, const float* __restrict__ bias1,
    float* __restrict__ C, int N)
{
    extern __shared__ char smem[];
    const uint32_t sb = smem_u32(smem);
    const int tid = threadIdx.x;
    const int wid = tid >> 5;
    const int lane = tid & 31;
    const int m0 = blockIdx.x * 128;
    const int n0 = blockIdx.y * 256;
    const int warp_m = wid >> 2;
    const int warp_n = wid & 3;

    auto load_chunk = [&](int c) {
        const int k0 = c * 32;
        const uint32_t st = sb + (uint32_t)(c % 3) * GS_STAGE;
#pragma unroll
        for (int it = 0; it < 12; it++) {
            int i = it * 256 + tid;
            if (i < 1024) {
                int row = i >> 3;
                int g = i & 7;
                int part = g >> 2;
                int kg = g & 3;
                const __nv_bfloat16* src =
                    (part ? Alo : Ahi) + (size_t)(m0 + row) * 512 + k0 + kg * 8;
                uint32_t dst = st + (uint32_t)(row * 128) +
                               ((uint32_t)(g ^ (row & 7)) << 4);
                asm volatile("cp.async.cg.shared.global [%0], [%1], 16;" :: "r"(dst), "l"(src));
            } else {
                int li = i - 1024;
                int row = li >> 3;
                int g = li & 7;
                int part = g >> 2;
                int kg = g & 3;
                const __nv_bfloat16* src =
                    (part ? Blo : Bhi) + (size_t)(n0 + row) * 512 + k0 + kg * 8;
                uint32_t dst = st + 16384u + (uint32_t)(row * 128) +
                               ((uint32_t)(g ^ (row & 7)) << 4);
                asm volatile("cp.async.cg.shared.global [%0], [%1], 16;" :: "r"(dst), "l"(src));
            }
        }
        asm volatile("cp.async.commit_group;" ::: "memory");
    };

    load_chunk(0);
    load_chunk(1);

    const int t = lane >> 3, trow = lane & 7;
    const int a_mpart = (t & 1) * 8 + trow;
    const int a_gsel = t >> 1;
    uint32_t a_row_off[4]; uint32_t a_sw[4];
#pragma unroll
    for (int mf = 0; mf < 4; mf++) {
        int ml = warp_m * 64 + mf * 16 + a_mpart;
        a_row_off[mf] = (uint32_t)(ml * 128);
        a_sw[mf] = (uint32_t)(ml & 7);
    }
    const int b_fragsel = t >> 1;
    const int b_gsel = t & 1;
    uint32_t b_row_off[4]; uint32_t b_sw[4];
#pragma unroll
    for (int nf2 = 0; nf2 < 4; nf2++) {
        int nl = warp_n * 64 + (nf2 * 2 + b_fragsel) * 8 + trow;
        b_row_off[nf2] = (uint32_t)(nl * 128) + 16384u;
        b_sw[nf2] = (uint32_t)(nl & 7);
    }

    float acc[4][8][4];
#pragma unroll
    for (int i = 0; i < 4; i++)
#pragma unroll
        for (int j = 0; j < 8; j++)
#pragma unroll
            for (int r = 0; r < 4; r++) acc[i][j][r] = 0.0f;

    for (int c = 0; c < FC_NCHUNK; c++) {
        if (c < FC_NCHUNK - 1)
            asm volatile("cp.async.wait_group 1;" ::: "memory");
        else
            asm volatile("cp.async.wait_group 0;" ::: "memory");
        __syncthreads();
        if (c + 2 < FC_NCHUNK) load_chunk(c + 2);

        const uint32_t st = sb + (uint32_t)(c % 3) * GS_STAGE;
#pragma unroll
        for (int ks = 0; ks < 2; ks++) {
            uint32_t ah[4][4], al[4][4];
#pragma unroll
            for (int mf = 0; mf < 4; mf++) {
                uint32_t Ghi = (uint32_t)(ks * 2 + a_gsel);
                uint32_t Glo = Ghi + 4u;
                ldsm_x4(ah[mf][0], ah[mf][1], ah[mf][2], ah[mf][3],
                        st + a_row_off[mf] + ((Ghi ^ a_sw[mf]) << 4));
                ldsm_x4(al[mf][0], al[mf][1], al[mf][2], al[mf][3],
                        st + a_row_off[mf] + ((Glo ^ a_sw[mf]) << 4));
            }
#pragma unroll
            for (int nf2 = 0; nf2 < 4; nf2++) {
                uint32_t bh[2][2], bl[2][2];
                uint32_t Ghi = (uint32_t)(ks * 2 + b_gsel);
                uint32_t Glo = Ghi + 4u;
                ldsm_x4(bh[0][0], bh[0][1], bh[1][0], bh[1][1],
                        st + b_row_off[nf2] + ((Ghi ^ b_sw[nf2]) << 4));
                ldsm_x4(bl[0][0], bl[0][1], bl[1][0], bl[1][1],
                        st + b_row_off[nf2] + ((Glo ^ b_sw[nf2]) << 4));
#pragma unroll
                for (int mf = 0; mf < 4; mf++)
#pragma unroll
                    for (int j = 0; j < 2; j++)
                        mma_bf16(acc[mf][nf2 * 2 + j], ah[mf], bh[j]);
#pragma unroll
                for (int mf = 0; mf < 4; mf++)
#pragma unroll
                    for (int j = 0; j < 2; j++)
                        mma_bf16(acc[mf][nf2 * 2 + j], al[mf], bh[j]);
#pragma unroll
                for (int mf = 0; mf < 4; mf++)
#pragma unroll
                    for (int j = 0; j < 2; j++)
                        mma_bf16(acc[mf][nf2 * 2 + j], ah[mf], bl[j]);
            }
        }
    }

    const int lrow = lane >> 2;
    const int lcol = (lane & 3) * 2;
#pragma unroll
    for (int mf = 0; mf < 4; mf++) {
        int r0 = m0 + warp_m * 64 + mf * 16 + lrow;
        float* crow0 = C + (size_t)r0 * N;
        float* crow1 = crow0 + (size_t)8 * N;
#pragma unroll
        for (int nf = 0; nf < 8; nf++) {
            int cn = n0 + warp_n * 64 + nf * 8 + lcol;
            float b0 = __ldg(bias0 + cn);
            float b1 = __ldg(bias0 + cn + 1);
            if (bias1) { b0 += __ldg(bias1 + cn); b1 += __ldg(bias1 + cn + 1); }
            float2 v0 = { acc[mf][nf][0] + b0, acc[mf][nf][1] + b1 };
            float2 v1 = { acc[mf][nf][2] + b0, acc[mf][nf][3] + b1 };
            *(float2*)(crow0 + cn) = v0;
            *(float2*)(crow1 + cn) = v1;
        }
    }
}

// ============================================================================
// K4: fp16 2-term GEMM. A single fp16, B fp16 hi/lo. C = A@(Bhi+Blo)^T + bias.
// Same tiling as gemm_mma; A lo-half of each SMEM row unused.
// ============================================================================
__global__ __launch_bounds__(256, 1) void gemm_f16_2t(
    const __half* __restrict__ A16,
    const __half* __restrict__ Bhi, const __half* __restrict__ Blo,
    const float* __restrict__ bias0, float* __restrict__ C, int N)
{
    extern __shared__ char smem[];
    const uint32_t sb = smem_u32(smem);
    const int tid = threadIdx.x;
    const int wid = tid >> 5;
    const int lane = tid & 31;
    const int m0 = blockIdx.x * 128;
    const int n0 = blockIdx.y * 256;
    const int warp_m = wid >> 2;
    const int warp_n = wid & 3;

    // per chunk: A 512 granules (hi only) + B 2048 = 2560 -> 10 per thread
    auto load_chunk = [&](int c) {
        const int k0 = c * 32;
        const uint32_t st = sb + (uint32_t)(c % 3) * GS_STAGE;
#pragma unroll
        for (int it = 0; it < 10; it++) {
            int i = it * 256 + tid;
            if (i < 512) {
                int row = i >> 2;          // 0..127
                int g = i & 3;             // 4 granules = 32 fp16 k's
                const __half* src = A16 + (size_t)(m0 + row) * 512 + k0 + g * 8;
                uint32_t dst = st + (uint32_t)(row * 128) +
                               ((uint32_t)(g ^ (row & 7)) << 4);
                asm volatile("cp.async.cg.shared.global [%0], [%1], 16;" :: "r"(dst), "l"(src));
            } else {
                int li = i - 512;
                int row = li >> 3;         // 0..255
                int g = li & 7;
                int part = g >> 2;
                int kg = g & 3;
                const __half* src =
                    (part ? Blo : Bhi) + (size_t)(n0 + row) * 512 + k0 + kg * 8;
                uint32_t dst = st + 16384u + (uint32_t)(row * 128) +
                               ((uint32_t)(g ^ (row & 7)) << 4);
                asm volatile("cp.async.cg.shared.global [%0], [%1], 16;" :: "r"(dst), "l"(src));
            }
        }
        asm volatile("cp.async.commit_group;" ::: "memory");
    };

    load_chunk(0);
    load_chunk(1);

    const int t = lane >> 3, trow = lane & 7;
    const int a_mpart = (t & 1) * 8 + trow;
    const int a_gsel = t >> 1;
    uint32_t a_row_off[4]; uint32_t a_sw[4];
#pragma unroll
    for (int mf = 0; mf < 4; mf++) {
        int ml = warp_m * 64 + mf * 16 + a_mpart;
        a_row_off[mf] = (uint32_t)(ml * 128);
        a_sw[mf] = (uint32_t)(ml & 7);
    }
    const int b_fragsel = t >> 1;
    const int b_gsel = t & 1;
    uint32_t b_row_off[4]; uint32_t b_sw[4];
#pragma unroll
    for (int nf2 = 0; nf2 < 4; nf2++) {
        int nl = warp_n * 64 + (nf2 * 2 + b_fragsel) * 8 + trow;
        b_row_off[nf2] = (uint32_t)(nl * 128) + 16384u;
        b_sw[nf2] = (uint32_t)(nl & 7);
    }

    float acc[4][8][4];
#pragma unroll
    for (int i = 0; i < 4; i++)
#pragma unroll
        for (int j = 0; j < 8; j++)
#pragma unroll
            for (int r = 0; r < 4; r++) acc[i][j][r] = 0.0f;

    for (int c = 0; c < FC_NCHUNK; c++) {
        if (c < FC_NCHUNK - 1)
            asm volatile("cp.async.wait_group 1;" ::: "memory");
        else
            asm volatile("cp.async.wait_group 0;" ::: "memory");
        __syncthreads();
        if (c + 2 < FC_NCHUNK) load_chunk(c + 2);

        const uint32_t st = sb + (uint32_t)(c % 3) * GS_STAGE;
#pragma unroll
        for (int ks = 0; ks < 2; ks++) {
            uint32_t ah[4][4];
#pragma unroll
            for (int mf = 0; mf < 4; mf++) {
                uint32_t Ghi = (uint32_t)(ks * 2 + a_gsel);   // 0..3: hi half only
                ldsm_x4(ah[mf][0], ah[mf][1], ah[mf][2], ah[mf][3],
                        st + a_row_off[mf] + ((Ghi ^ a_sw[mf]) << 4));
            }
#pragma unroll
            for (int nf2 = 0; nf2 < 4; nf2++) {
                uint32_t bh[2][2], bl[2][2];
                uint32_t Ghi = (uint32_t)(ks * 2 + b_gsel);
                uint32_t Glo = Ghi + 4u;
                ldsm_x4(bh[0][0], bh[0][1], bh[1][0], bh[1][1],
                        st + b_row_off[nf2] + ((Ghi ^ b_sw[nf2]) << 4));
                ldsm_x4(bl[0][0], bl[0][1], bl[1][0], bl[1][1],
                        st + b_row_off[nf2] + ((Glo ^ b_sw[nf2]) << 4));
#pragma unroll
                for (int mf = 0; mf < 4; mf++)
#pragma unroll
                    for (int j = 0; j < 2; j++)
                        mma_f16(acc[mf][nf2 * 2 + j], ah[mf], bh[j]);   // A*Bhi
#pragma unroll
                for (int mf = 0; mf < 4; mf++)
#pragma unroll
                    for (int j = 0; j < 2; j++)
                        mma_f16(acc[mf][nf2 * 2 + j], ah[mf], bl[j]);   // A*Blo
            }
        }
    }

    const int lrow = lane >> 2;
    const int lcol = (lane & 3) * 2;
#pragma unroll
    for (int mf = 0; mf < 4; mf++) {
        int r0 = m0 + warp_m * 64 + mf * 16 + lrow;
        float* crow0 = C + (size_t)r0 * N;
        float* crow1 = crow0 + (size_t)8 * N;
#pragma unroll
        for (int nf = 0; nf < 8; nf++) {
            int cn = n0 + warp_n * 64 + nf * 8 + lcol;
            float b0 = __ldg(bias0 + cn);
            float b1 = __ldg(bias0 + cn + 1);
            float2 v0 = { acc[mf][nf][0] + b0, acc[mf][nf][1] + b1 };
            float2 v1 = { acc[mf][nf][2] + b0, acc[mf][nf][3] + b1 };
            *(float2*)(crow0 + cn) = v0;
            *(float2*)(crow1 + cn) = v1;
        }
    }
}

// ============================================================================
// launch
// ============================================================================
extern "C" void kernel_launch(void* const* d_in, const int* in_sizes, int n_in,
                              void* d_out, int out_size)
{
    const int*   x    = (const int*)d_in[0];
    const float* z    = (const float*)d_in[1];
    const float* emb  = (const float*)d_in[2];
    const float* W_ih = (const float*)d_in[3];
    const float* W_hh = (const float*)d_in[4];
    const float* b_ih = (const float*)d_in[5];
    const float* b_hh = (const float*)d_in[6];
    const float* ln_g = (const float*)d_in[7];
    const float* ln_b = (const float*)d_in[8];
    const float* fc_W = (const float*)d_in[9];
    const float* fc_b = (const float*)d_in[10];
    float* out = (float*)d_out;

    float* xg_p;
    __nv_bfloat16 *ahi_p, *alo_p, *ihhi_p, *ihlo_p;
    __half *n16_p, *w16hi_p, *w16lo_p;
    cudaGetSymbolAddress((void**)&xg_p, g_xg);
    cudaGetSymbolAddress((void**)&ahi_p, g_ahi);
    cudaGetSymbolAddress((void**)&alo_p, g_alo);
    cudaGetSymbolAddress((void**)&ihhi_p, g_ihhi);
    cudaGetSymbolAddress((void**)&ihlo_p, g_ihlo);
    cudaGetSymbolAddress((void**)&n16_p, g_n16);
    cudaGetSymbolAddress((void**)&w16hi_p, g_w16hi);
    cudaGetSymbolAddress((void**)&w16lo_p, g_w16lo);

    const int gemm_smem = 3 * GS_STAGE;   // 147456
    cudaFuncSetAttribute(gemm_mma, cudaFuncAttributeMaxDynamicSharedMemorySize, gemm_smem);
    cudaFuncSetAttribute(gemm_f16_2t, cudaFuncAttributeMaxDynamicSharedMemorySize, gemm_smem);

    // K0a: fc_W -> fp16 hi/lo
    conv_split_h<<<2048, 256>>>(fc_W, w16hi_p, w16lo_p, (unsigned)(VV * HH / 4));
    // K0b: W_ih -> bf16 hi/lo
    conv_split<<<256, 256>>>(W_ih, ihhi_p, ihlo_p, (unsigned)(GG * EE / 4));
    // K0c: gathered embedding -> bf16 hi/lo
    conv_emb<<<SS * BB, 128>>>(emb, x);

    // K1: input-side gate GEMM (bf16 3-term) -> g_xg
    {
        dim3 grid((SS * BB) / 128, GG / 256);  // (16, 8)
        gemm_mma<<<grid, 256, gemm_smem>>>(ahi_p, alo_p, ihhi_p, ihlo_p,
                                           b_ih, b_hh, xg_p, GG);
    }

    // K2: persistent LSTM recurrence (R9)
    {
        const int smem = (16 * HPAD * 2 + 4096 + 256 + 64) * 4;
        cudaFuncSetAttribute(lstm_kernel, cudaFuncAttributeMaxDynamicSharedMemorySize, smem);
        lstm_kernel<<<128, 256, smem>>>(W_hh, z, out + (size_t)BB * SS * VV);
    }

    // K3: layernorm -> fp16
    ln_kernel<<<BB * SS, 128>>>(ln_g, ln_b);

    // K4: FC logits GEMM (fp16 2-term)
    {
        dim3 grid((SS * BB) / 128, VV / 256);  // (16, 125)
        gemm_f16_2t<<<grid, 256, gemm_smem>>>(n16_p, w16hi_p, w16lo_p,
                                              fc_b, out, VV);
    }
}

// round 15
// speedup vs baseline: 1.3090x; 1.1590x over previous
#include <cuda_runtime.h>
#include <cuda_bf16.h>
#include <cuda_fp16.h>
#include <cstdint>

// Problem constants
#define SS   128
#define BB   16
#define EE   512
#define HH   512
#define GG   2048
#define VV   32000
#define LNEPS 1e-5f
#define HPAD 514

// ---------------- scratch (device globals; 256B-aligned) ----------------
__device__ __align__(256) float g_xg[SS * BB * GG];     // (s,b,g) gate preacts
__device__ __align__(256) float g_hs[BB * SS * HH];     // hidden states
__device__ __align__(256) float g_hbuf[2][BB * HH];     // ping-pong h broadcast
__device__ __align__(256) unsigned g_cnt8[2048];        // 8 counters, 1KB apart
__device__ unsigned g_master;
__device__ unsigned g_bar_gen;
// bf16 split operands (K1 path — proven)
__device__ __align__(256) __nv_bfloat16 g_ahi[SS * BB * EE];
__device__ __align__(256) __nv_bfloat16 g_alo[SS * BB * EE];
__device__ __align__(256) __nv_bfloat16 g_ihhi[GG * EE];
__device__ __align__(256) __nv_bfloat16 g_ihlo[GG * EE];
// fp16 operands (K4 path — 1-term)
__device__ __align__(256) __half g_n16[BB * SS * HH];   // LN out, single fp16
__device__ __align__(256) __half g_w16[VV * HH];        // fc_W single fp16

__device__ __forceinline__ float sigf(float x) { return 1.0f / (1.0f + __expf(-x)); }
__device__ __forceinline__ float tanhfast(float x) { return 2.0f / (1.0f + __expf(-2.0f * x)) - 1.0f; }

__device__ __forceinline__ uint32_t smem_u32(const void* p) {
    uint32_t a;
    asm("{ .reg .u64 t; cvta.to.shared.u64 t, %1; cvt.u32.u64 %0, t; }" : "=r"(a) : "l"(p));
    return a;
}

__device__ __forceinline__ void split_bf16(float v, __nv_bfloat16& h, __nv_bfloat16& l) {
    h = __float2bfloat16_rn(v);
    l = __float2bfloat16_rn(v - __bfloat162float(h));
}

// ============================================================================
// fp32 -> bf16 hi/lo split (grid-stride, float4) — K1 operands
// ============================================================================
__global__ __launch_bounds__(256) void conv_split(
    const float* __restrict__ src, __nv_bfloat16* __restrict__ dhi,
    __nv_bfloat16* __restrict__ dlo, unsigned total4)
{
    const float4* s4 = (const float4*)src;
    for (unsigned p = blockIdx.x * blockDim.x + threadIdx.x; p < total4;
         p += gridDim.x * blockDim.x) {
        float4 v = s4[p];
        __nv_bfloat16 h0, h1, h2, h3, l0, l1, l2, l3;
        split_bf16(v.x, h0, l0); split_bf16(v.y, h1, l1);
        split_bf16(v.z, h2, l2); split_bf16(v.w, h3, l3);
        ((__nv_bfloat162*)dhi)[p * 2 + 0] = __nv_bfloat162(h0, h1);
        ((__nv_bfloat162*)dhi)[p * 2 + 1] = __nv_bfloat162(h2, h3);
        ((__nv_bfloat162*)dlo)[p * 2 + 0] = __nv_bfloat162(l0, l1);
        ((__nv_bfloat162*)dlo)[p * 2 + 1] = __nv_bfloat162(l2, l3);
    }
}

// ============================================================================
// fp32 -> single fp16 (grid-stride, float4) — K4 weights
// ============================================================================
__global__ __launch_bounds__(256) void conv_h1(
    const float* __restrict__ src, __half* __restrict__ dst, unsigned total4)
{
    const float4* s4 = (const float4*)src;
    for (unsigned p = blockIdx.x * blockDim.x + threadIdx.x; p < total4;
         p += gridDim.x * blockDim.x) {
        float4 v = s4[p];
        ((__half2*)dst)[p * 2 + 0] = __half2(__float2half_rn(v.x), __float2half_rn(v.y));
        ((__half2*)dst)[p * 2 + 1] = __half2(__float2half_rn(v.z), __float2half_rn(v.w));
    }
}

// ============================================================================
// Embedding gather + bf16 hi/lo split. Row m -> token x[(m&15)*SS + (m>>4)].
// ============================================================================
__global__ __launch_bounds__(128) void conv_emb(
    const float* __restrict__ emb, const int* __restrict__ x)
{
    const int m = blockIdx.x;
    const int tid = threadIdx.x;
    const int token = x[(m & 15) * SS + (m >> 4)];
    float4 v = *(const float4*)(emb + (size_t)token * 512 + tid * 4);
    __nv_bfloat16 h0, h1, h2, h3, l0, l1, l2, l3;
    split_bf16(v.x, h0, l0); split_bf16(v.y, h1, l1);
    split_bf16(v.z, h2, l2); split_bf16(v.w, h3, l3);
    ((__nv_bfloat162*)(g_ahi + (size_t)m * 512))[tid * 2 + 0] = __nv_bfloat162(h0, h1);
    ((__nv_bfloat162*)(g_ahi + (size_t)m * 512))[tid * 2 + 1] = __nv_bfloat162(h2, h3);
    ((__nv_bfloat162*)(g_alo + (size_t)m * 512))[tid * 2 + 0] = __nv_bfloat162(l0, l1);
    ((__nv_bfloat162*)(g_alo + (size_t)m * 512))[tid * 2 + 1] = __nv_bfloat162(l2, l3);
}

// ============================================================================
// Persistent LSTM recurrence — exact R9 version (best measured)
// ============================================================================
__global__ __launch_bounds__(256, 1) void lstm_kernel(
    const float* __restrict__ Whh,
    const float* __restrict__ z,
    float* __restrict__ out_hc)
{
    extern __shared__ float sm[];
    float* Wsm = sm;
    float* hsm = Wsm + 16 * HPAD;
    float* red = hsm + 16 * HPAD;
    float* pre = red + 4096;
    float* cst = pre + 256;

    const int tid = threadIdx.x;
    const int cta = blockIdx.x;

    unsigned gen0 = 0;
    if (tid == 0) gen0 = *((volatile unsigned*)&g_bar_gen);

    for (int i = tid; i < 16 * 128; i += 256) {
        int r = i >> 7;
        int e4 = (i & 127) * 4;
        int grow = (r >> 2) * 512 + cta * 4 + (r & 3);
        float4 w = *(const float4*)(Whh + (size_t)grow * 512 + e4);
        float* dst = &Wsm[r * HPAD + e4];
        dst[0] = w.x; dst[1] = w.y; dst[2] = w.z; dst[3] = w.w;
    }
    for (int i = tid; i < 16 * 128; i += 256) {
        int b = i >> 7;
        int e4 = (i & 127) * 4;
        float4 h = *(const float4*)(z + b * 1024 + e4);
        float* dst = &hsm[b * HPAD + e4];
        dst[0] = h.x; dst[1] = h.y; dst[2] = h.z; dst[3] = h.w;
    }
    if (tid < 64) {
        int ul = tid >> 4, b = tid & 15;
        cst[ul * 16 + b] = z[b * 1024 + 512 + cta * 4 + ul];
    }
    __syncthreads();

    const int kq = tid >> 4;
    const int rq = (tid >> 2) & 3;
    const int bq = tid & 3;
    const int xr = tid >> 4, xb = tid & 15;
    const float* xg_addr = &g_xg[(size_t)xb * 2048 + (xr >> 2) * 512 + cta * 4 + (xr & 3)];

    for (int t = 0; t < SS; t++) {
        float xg_v = __ldg(xg_addr + (size_t)t * 16 * 2048);

        float acc00=0,acc01=0,acc02=0,acc03=0;
        float acc10=0,acc11=0,acc12=0,acc13=0;
        float acc20=0,acc21=0,acc22=0,acc23=0;
        float acc30=0,acc31=0,acc32=0,acc33=0;
        const float* h0p = &hsm[(bq * 4 + 0) * HPAD];
        const float* h1p = &hsm[(bq * 4 + 1) * HPAD];
        const float* h2p = &hsm[(bq * 4 + 2) * HPAD];
        const float* h3p = &hsm[(bq * 4 + 3) * HPAD];
        const float* w0p = &Wsm[(rq * 4 + 0) * HPAD];
        const float* w1p = &Wsm[(rq * 4 + 1) * HPAD];
        const float* w2p = &Wsm[(rq * 4 + 2) * HPAD];
        const float* w3p = &Wsm[(rq * 4 + 3) * HPAD];
#pragma unroll 4
        for (int j = 0; j < 16; j++) {
            int e = (kq + 16 * j) * 2;
            float2 hv0 = *(const float2*)(h0p + e);
            float2 hv1 = *(const float2*)(h1p + e);
            float2 hv2 = *(const float2*)(h2p + e);
            float2 hv3 = *(const float2*)(h3p + e);
            float2 wv;
            wv = *(const float2*)(w0p + e);
            acc00 += wv.x*hv0.x + wv.y*hv0.y; acc01 += wv.x*hv1.x + wv.y*hv1.y;
            acc02 += wv.x*hv2.x + wv.y*hv2.y; acc03 += wv.x*hv3.x + wv.y*hv3.y;
            wv = *(const float2*)(w1p + e);
            acc10 += wv.x*hv0.x + wv.y*hv0.y; acc11 += wv.x*hv1.x + wv.y*hv1.y;
            acc12 += wv.x*hv2.x + wv.y*hv2.y; acc13 += wv.x*hv3.x + wv.y*hv3.y;
            wv = *(const float2*)(w2p + e);
            acc20 += wv.x*hv0.x + wv.y*hv0.y; acc21 += wv.x*hv1.x + wv.y*hv1.y;
            acc22 += wv.x*hv2.x + wv.y*hv2.y; acc23 += wv.x*hv3.x + wv.y*hv3.y;
            wv = *(const float2*)(w3p + e);
            acc30 += wv.x*hv0.x + wv.y*hv0.y; acc31 += wv.x*hv1.x + wv.y*hv1.y;
            acc32 += wv.x*hv2.x + wv.y*hv2.y; acc33 += wv.x*hv3.x + wv.y*hv3.y;
        }
        {
            float* rbase = &red[kq * 256];
            int r0 = rq * 4, b0 = bq * 4;
            rbase[(r0+0)*16 + b0+0]=acc00; rbase[(r0+0)*16 + b0+1]=acc01; rbase[(r0+0)*16 + b0+2]=acc02; rbase[(r0+0)*16 + b0+3]=acc03;
            rbase[(r0+1)*16 + b0+0]=acc10; rbase[(r0+1)*16 + b0+1]=acc11; rbase[(r0+1)*16 + b0+2]=acc12; rbase[(r0+1)*16 + b0+3]=acc13;
            rbase[(r0+2)*16 + b0+0]=acc20; rbase[(r0+2)*16 + b0+1]=acc21; rbase[(r0+2)*16 + b0+2]=acc22; rbase[(r0+2)*16 + b0+3]=acc23;
            rbase[(r0+3)*16 + b0+0]=acc30; rbase[(r0+3)*16 + b0+1]=acc31; rbase[(r0+3)*16 + b0+2]=acc32; rbase[(r0+3)*16 + b0+3]=acc33;
        }
        __syncthreads();

        {
            float s = 0.0f;
#pragma unroll
            for (int k2 = 0; k2 < 16; k2++) s += red[k2 * 256 + xr * 16 + xb];
            pre[xr * 16 + xb] = s + xg_v;
        }
        __syncthreads();

        if (tid < 64) {
            int ul = tid >> 4, b = tid & 15;
            int ug = cta * 4 + ul;
            float iv = pre[(0  + ul) * 16 + b];
            float fv = pre[(4  + ul) * 16 + b];
            float gv = pre[(8  + ul) * 16 + b];
            float ov = pre[(12 + ul) * 16 + b];
            float c = cst[ul * 16 + b];
            c = sigf(fv) * c + sigf(iv) * tanhfast(gv);
            float hN = sigf(ov) * tanhfast(c);
            cst[ul * 16 + b] = c;
            g_hbuf[t & 1][b * 512 + ug] = hN;
            g_hs[(size_t)b * (SS * HH) + t * 512 + ug] = hN;
            if (t == SS - 1) {
                out_hc[b * 1024 + ug] = hN;
                out_hc[b * 1024 + 512 + ug] = c;
            }
        }

        if (t < SS - 1) {
            __threadfence();
            __syncthreads();
            if (tid == 0) {
                unsigned target = gen0 + (unsigned)t + 1u;
                unsigned a = atomicAdd(&g_cnt8[(cta & 7) << 8], 1u);
                if (a == 15u) {
                    unsigned m = atomicAdd(&g_master, 1u);
                    if (m == 7u) {
#pragma unroll
                        for (int q = 0; q < 8; q++)
                            atomicExch(&g_cnt8[q << 8], 0u);
                        atomicExch(&g_master, 0u);
                        __threadfence();
                        atomicAdd(&g_bar_gen, 1u);
                    }
                }
                while ((int)(*((volatile unsigned*)&g_bar_gen) - target) < 0) { }
            }
            __syncthreads();
            const float2* src = (const float2*)(&g_hbuf[t & 1][0]);
            for (int i = tid; i < 4096; i += 256) {
                int b = i >> 8;
                int e2 = i & 255;
                float2 v = __ldcg(src + i);
                *(float2*)&hsm[b * HPAD + e2 * 2] = v;
            }
            __syncthreads();
        }
    }
}

// ============================================================================
// LayerNorm -> single fp16 output
// ============================================================================
__global__ __launch_bounds__(128) void ln_kernel(
    const float* __restrict__ gamma, const float* __restrict__ beta)
{
    __shared__ float rs[4], rs2[4];
    const int m = blockIdx.x;
    const int tid = threadIdx.x;
    const float* row = g_hs + (size_t)m * 512;

    float4 v = *(const float4*)(row + tid * 4);
    float s  = v.x + v.y + v.z + v.w;
    float s2 = v.x * v.x + v.y * v.y + v.z * v.z + v.w * v.w;

    const int lane = tid & 31, w = tid >> 5;
#pragma unroll
    for (int o = 16; o; o >>= 1) {
        s  += __shfl_xor_sync(0xffffffffu, s, o);
        s2 += __shfl_xor_sync(0xffffffffu, s2, o);
    }
    if (lane == 0) { rs[w] = s; rs2[w] = s2; }
    __syncthreads();
    s  = rs[0] + rs[1] + rs[2] + rs[3];
    s2 = rs2[0] + rs2[1] + rs2[2] + rs2[3];

    float mu = s * (1.0f / 512.0f);
    float var = s2 * (1.0f / 512.0f) - mu * mu;
    float inv = rsqrtf(var + LNEPS);

    float4 g4 = *(const float4*)(gamma + tid * 4);
    float4 b4 = *(const float4*)(beta + tid * 4);
    float o0 = (v.x - mu) * inv * g4.x + b4.x;
    float o1 = (v.y - mu) * inv * g4.y + b4.y;
    float o2 = (v.z - mu) * inv * g4.z + b4.z;
    float o3 = (v.w - mu) * inv * g4.w + b4.w;

    __half2* np = (__half2*)(g_n16 + (size_t)m * 512);
    np[tid * 2 + 0] = __half2(__float2half_rn(o0), __float2half_rn(o1));
    np[tid * 2 + 1] = __half2(__float2half_rn(o2), __float2half_rn(o3));
}

// ============================================================================
// Shared GEMM helpers
// ============================================================================
#define GS_STAGE 49152
#define FC_NCHUNK 16

__device__ __forceinline__ void ldsm_x4(uint32_t& r0, uint32_t& r1, uint32_t& r2,
                                        uint32_t& r3, uint32_t addr) {
    asm volatile("ldmatrix.sync.aligned.m8n8.x4.shared.b16 {%0,%1,%2,%3}, [%4];"
                 : "=r"(r0), "=r"(r1), "=r"(r2), "=r"(r3) : "r"(addr));
}

__device__ __forceinline__ void mma_bf16(float* c, const uint32_t* a, const uint32_t* b) {
    asm volatile(
        "mma.sync.aligned.m16n8k16.row.col.f32.bf16.bf16.f32 "
        "{%0,%1,%2,%3}, {%4,%5,%6,%7}, {%8,%9}, {%0,%1,%2,%3};"
        : "+f"(c[0]), "+f"(c[1]), "+f"(c[2]), "+f"(c[3])
        : "r"(a[0]), "r"(a[1]), "r"(a[2]), "r"(a[3]), "r"(b[0]), "r"(b[1]));
}

__device__ __forceinline__ void mma_f16(float* c, const uint32_t* a, const uint32_t* b) {
    asm volatile(
        "mma.sync.aligned.m16n8k16.row.col.f32.f16.f16.f32 "
        "{%0,%1,%2,%3}, {%4,%5,%6,%7}, {%8,%9}, {%0,%1,%2,%3};"
        : "+f"(c[0]), "+f"(c[1]), "+f"(c[2]), "+f"(c[3])
        : "r"(a[0]), "r"(a[1]), "r"(a[2]), "r"(a[3]), "r"(b[0]), "r"(b[1]));
}

// ============================================================================
// K1: bf16 3-term GEMM — exact R9 config (proven). C = A@B^T + bias0 + bias1
// ============================================================================
__global__ __launch_bounds__(256, 1) void gemm_mma(
    const __nv_bfloat16* __restrict__ Ahi, const __nv_bfloat16* __restrict__ Alo,
    const __nv_bfloat16* __restrict__ Bhi, const __nv_bfloat16* __restrict__ Blo,
    const float* __restrict__ bias0, const float* __restrict__ bias1,
    float* __restrict__ C, int N)
{
    extern __shared__ char smem[];
    const uint32_t sb = smem_u32(smem);
    const int tid = threadIdx.x;
    const int wid = tid >> 5;
    const int lane = tid & 31;
    const int m0 = blockIdx.x * 128;
    const int n0 = blockIdx.y * 256;
    const int warp_m = wid >> 2;
    const int warp_n = wid & 3;

    auto load_chunk = [&](int c) {
        const int k0 = c * 32;
        const uint32_t st = sb + (uint32_t)(c % 3) * GS_STAGE;
#pragma unroll
        for (int it = 0; it < 12; it++) {
            int i = it * 256 + tid;
            if (i < 1024) {
                int row = i >> 3;
                int g = i & 7;
                int part = g >> 2;
                int kg = g & 3;
                const __nv_bfloat16* src =
                    (part ? Alo : Ahi) + (size_t)(m0 + row) * 512 + k0 + kg * 8;
                uint32_t dst = st + (uint32_t)(row * 128) +
                               ((uint32_t)(g ^ (row & 7)) << 4);
                asm volatile("cp.async.cg.shared.global [%0], [%1], 16;" :: "r"(dst), "l"(src));
            } else {
                int li = i - 1024;
                int row = li >> 3;
                int g = li & 7;
                int part = g >> 2;
                int kg = g & 3;
                const __nv_bfloat16* src =
                    (part ? Blo : Bhi) + (size_t)(n0 + row) * 512 + k0 + kg * 8;
                uint32_t dst = st + 16384u + (uint32_t)(row * 128) +
                               ((uint32_t)(g ^ (row & 7)) << 4);
                asm volatile("cp.async.cg.shared.global [%0], [%1], 16;" :: "r"(dst), "l"(src));
            }
        }
        asm volatile("cp.async.commit_group;" ::: "memory");
    };

    load_chunk(0);
    load_chunk(1);

    const int t = lane >> 3, trow = lane & 7;
    const int a_mpart = (t & 1) * 8 + trow;
    const int a_gsel = t >> 1;
    uint32_t a_row_off[4]; uint32_t a_sw[4];
#pragma unroll
    for (int mf = 0; mf < 4; mf++) {
        int ml = warp_m * 64 + mf * 16 + a_mpart;
        a_row_off[mf] = (uint32_t)(ml * 128);
        a_sw[mf] = (uint32_t)(ml & 7);
    }
    const int b_fragsel = t >> 1;
    const int b_gsel = t & 1;
    uint32_t b_row_off[4]; uint32_t b_sw[4];
#pragma unroll
    for (int nf2 = 0; nf2 < 4; nf2++) {
        int nl = warp_n * 64 + (nf2 * 2 + b_fragsel) * 8 + trow;
        b_row_off[nf2] = (uint32_t)(nl * 128) + 16384u;
        b_sw[nf2] = (uint32_t)(nl & 7);
    }

    float acc[4][8][4];
#pragma unroll
    for (int i = 0; i < 4; i++)
#pragma unroll
        for (int j = 0; j < 8; j++)
#pragma unroll
            for (int r = 0; r < 4; r++) acc[i][j][r] = 0.0f;

    for (int c = 0; c < FC_NCHUNK; c++) {
        if (c < FC_NCHUNK - 1)
            asm volatile("cp.async.wait_group 1;" ::: "memory");
        else
            asm volatile("cp.async.wait_group 0;" ::: "memory");
        __syncthreads();
        if (c + 2 < FC_NCHUNK) load_chunk(c + 2);

        const uint32_t st = sb + (uint32_t)(c % 3) * GS_STAGE;
#pragma unroll
        for (int ks = 0; ks < 2; ks++) {
            uint32_t ah[4][4], al[4][4];
#pragma unroll
            for (int mf = 0; mf < 4; mf++) {
                uint32_t Ghi = (uint32_t)(ks * 2 + a_gsel);
                uint32_t Glo = Ghi + 4u;
                ldsm_x4(ah[mf][0], ah[mf][1], ah[mf][2], ah[mf][3],
                        st + a_row_off[mf] + ((Ghi ^ a_sw[mf]) << 4));
                ldsm_x4(al[mf][0], al[mf][1], al[mf][2], al[mf][3],
                        st + a_row_off[mf] + ((Glo ^ a_sw[mf]) << 4));
            }
#pragma unroll
            for (int nf2 = 0; nf2 < 4; nf2++) {
                uint32_t bh[2][2], bl[2][2];
                uint32_t Ghi = (uint32_t)(ks * 2 + b_gsel);
                uint32_t Glo = Ghi + 4u;
                ldsm_x4(bh[0][0], bh[0][1], bh[1][0], bh[1][1],
                        st + b_row_off[nf2] + ((Ghi ^ b_sw[nf2]) << 4));
                ldsm_x4(bl[0][0], bl[0][1], bl[1][0], bl[1][1],
                        st + b_row_off[nf2] + ((Glo ^ b_sw[nf2]) << 4));
#pragma unroll
                for (int mf = 0; mf < 4; mf++)
#pragma unroll
                    for (int j = 0; j < 2; j++)
                        mma_bf16(acc[mf][nf2 * 2 + j], ah[mf], bh[j]);
#pragma unroll
                for (int mf = 0; mf < 4; mf++)
#pragma unroll
                    for (int j = 0; j < 2; j++)
                        mma_bf16(acc[mf][nf2 * 2 + j], al[mf], bh[j]);
#pragma unroll
                for (int mf = 0; mf < 4; mf++)
#pragma unroll
                    for (int j = 0; j < 2; j++)
                        mma_bf16(acc[mf][nf2 * 2 + j], ah[mf], bl[j]);
            }
        }
    }

    const int lrow = lane >> 2;
    const int lcol = (lane & 3) * 2;
#pragma unroll
    for (int mf = 0; mf < 4; mf++) {
        int r0 = m0 + warp_m * 64 + mf * 16 + lrow;
        float* crow0 = C + (size_t)r0 * N;
        float* crow1 = crow0 + (size_t)8 * N;
#pragma unroll
        for (int nf = 0; nf < 8; nf++) {
            int cn = n0 + warp_n * 64 + nf * 8 + lcol;
            float b0 = __ldg(bias0 + cn);
            float b1 = __ldg(bias0 + cn + 1);
            if (bias1) { b0 += __ldg(bias1 + cn); b1 += __ldg(bias1 + cn + 1); }
            float2 v0 = { acc[mf][nf][0] + b0, acc[mf][nf][1] + b1 };
            float2 v1 = { acc[mf][nf][2] + b0, acc[mf][nf][3] + b1 };
            *(float2*)(crow0 + cn) = v0;
            *(float2*)(crow1 + cn) = v1;
        }
    }
}

// ============================================================================
// K4: fp16 1-term GEMM. A and B single fp16. C = A@B^T + bias.
// Trimmed copy of the proven 2-term kernel (lo halves never loaded/read).
// ============================================================================
__global__ __launch_bounds__(256, 1) void gemm_f16_1t(
    const __half* __restrict__ A16, const __half* __restrict__ B16,
    const float* __restrict__ bias0, float* __restrict__ C, int N)
{
    extern __shared__ char smem[];
    const uint32_t sb = smem_u32(smem);
    const int tid = threadIdx.x;
    const int wid = tid >> 5;
    const int lane = tid & 31;
    const int m0 = blockIdx.x * 128;
    const int n0 = blockIdx.y * 256;
    const int warp_m = wid >> 2;
    const int warp_n = wid & 3;

    // per chunk: A 512 granules + B 1024 = 1536 -> 6 per thread
    auto load_chunk = [&](int c) {
        const int k0 = c * 32;
        const uint32_t st = sb + (uint32_t)(c % 3) * GS_STAGE;
#pragma unroll
        for (int it = 0; it < 6; it++) {
            int i = it * 256 + tid;
            if (i < 512) {
                int row = i >> 2;          // 0..127
                int g = i & 3;
                const __half* src = A16 + (size_t)(m0 + row) * 512 + k0 + g * 8;
                uint32_t dst = st + (uint32_t)(row * 128) +
                               ((uint32_t)(g ^ (row & 7)) << 4);
                asm volatile("cp.async.cg.shared.global [%0], [%1], 16;" :: "r"(dst), "l"(src));
            } else {
                int li = i - 512;
                int row = li >> 2;         // 0..255
                int g = li & 3;
                const __half* src = B16 + (size_t)(n0 + row) * 512 + k0 + g * 8;
                uint32_t dst = st + 16384u + (uint32_t)(row * 128) +
                               ((uint32_t)(g ^ (row & 7)) << 4);
                asm volatile("cp.async.cg.shared.global [%0], [%1], 16;" :: "r"(dst), "l"(src));
            }
        }
        asm volatile("cp.async.commit_group;" ::: "memory");
    };

    load_chunk(0);
    load_chunk(1);

    const int t = lane >> 3, trow = lane & 7;
    const int a_mpart = (t & 1) * 8 + trow;
    const int a_gsel = t >> 1;
    uint32_t a_row_off[4]; uint32_t a_sw[4];
#pragma unroll
    for (int mf = 0; mf < 4; mf++) {
        int ml = warp_m * 64 + mf * 16 + a_mpart;
        a_row_off[mf] = (uint32_t)(ml * 128);
        a_sw[mf] = (uint32_t)(ml & 7);
    }
    const int b_fragsel = t >> 1;
    const int b_gsel = t & 1;
    uint32_t b_row_off[4]; uint32_t b_sw[4];
#pragma unroll
    for (int nf2 = 0; nf2 < 4; nf2++) {
        int nl = warp_n * 64 + (nf2 * 2 + b_fragsel) * 8 + trow;
        b_row_off[nf2] = (uint32_t)(nl * 128) + 16384u;
        b_sw[nf2] = (uint32_t)(nl & 7);
    }

    float acc[4][8][4];
#pragma unroll
    for (int i = 0; i < 4; i++)
#pragma unroll
        for (int j = 0; j < 8; j++)
#pragma unroll
            for (int r = 0; r < 4; r++) acc[i][j][r] = 0.0f;

    for (int c = 0; c < FC_NCHUNK; c++) {
        if (c < FC_NCHUNK - 1)
            asm volatile("cp.async.wait_group 1;" ::: "memory");
        else
            asm volatile("cp.async.wait_group 0;" ::: "memory");
        __syncthreads();
        if (c + 2 < FC_NCHUNK) load_chunk(c + 2);

        const uint32_t st = sb + (uint32_t)(c % 3) * GS_STAGE;
#pragma unroll
        for (int ks = 0; ks < 2; ks++) {
            uint32_t ah[4][4];
#pragma unroll
            for (int mf = 0; mf < 4; mf++) {
                uint32_t Ghi = (uint32_t)(ks * 2 + a_gsel);
                ldsm_x4(ah[mf][0], ah[mf][1], ah[mf][2], ah[mf][3],
                        st + a_row_off[mf] + ((Ghi ^ a_sw[mf]) << 4));
            }
#pragma unroll
            for (int nf2 = 0; nf2 < 4; nf2++) {
                uint32_t bh[2][2];
                uint32_t Ghi = (uint32_t)(ks * 2 + b_gsel);
                ldsm_x4(bh[0][0], bh[0][1], bh[1][0], bh[1][1],
                        st + b_row_off[nf2] + ((Ghi ^ b_sw[nf2]) << 4));
#pragma unroll
                for (int mf = 0; mf < 4; mf++)
#pragma unroll
                    for (int j = 0; j < 2; j++)
                        mma_f16(acc[mf][nf2 * 2 + j], ah[mf], bh[j]);
            }
        }
    }

    const int lrow = lane >> 2;
    const int lcol = (lane & 3) * 2;
#pragma unroll
    for (int mf = 0; mf < 4; mf++) {
        int r0 = m0 + warp_m * 64 + mf * 16 + lrow;
        float* crow0 = C + (size_t)r0 * N;
        float* crow1 = crow0 + (size_t)8 * N;
#pragma unroll
        for (int nf = 0; nf < 8; nf++) {
            int cn = n0 + warp_n * 64 + nf * 8 + lcol;
            float b0 = __ldg(bias0 + cn);
            float b1 = __ldg(bias0 + cn + 1);
            float2 v0 = { acc[mf][nf][0] + b0, acc[mf][nf][1] + b1 };
            float2 v1 = { acc[mf][nf][2] + b0, acc[mf][nf][3] + b1 };
            *(float2*)(crow0 + cn) = v0;
            *(float2*)(crow1 + cn) = v1;
        }
    }
}

// ============================================================================
// launch
// ============================================================================
extern "C" void kernel_launch(void* const* d_in, const int* in_sizes, int n_in,
                              void* d_out, int out_size)
{
    const int*   x    = (const int*)d_in[0];
    const float* z    = (const float*)d_in[1];
    const float* emb  = (const float*)d_in[2];
    const float* W_ih = (const float*)d_in[3];
    const float* W_hh = (const float*)d_in[4];
    const float* b_ih = (const float*)d_in[5];
    const float* b_hh = (const float*)d_in[6];
    const float* ln_g = (const float*)d_in[7];
    const float* ln_b = (const float*)d_in[8];
    const float* fc_W = (const float*)d_in[9];
    const float* fc_b = (const float*)d_in[10];
    float* out = (float*)d_out;

    float* xg_p;
    __nv_bfloat16 *ahi_p, *alo_p, *ihhi_p, *ihlo_p;
    __half *n16_p, *w16_p;
    cudaGetSymbolAddress((void**)&xg_p, g_xg);
    cudaGetSymbolAddress((void**)&ahi_p, g_ahi);
    cudaGetSymbolAddress((void**)&alo_p, g_alo);
    cudaGetSymbolAddress((void**)&ihhi_p, g_ihhi);
    cudaGetSymbolAddress((void**)&ihlo_p, g_ihlo);
    cudaGetSymbolAddress((void**)&n16_p, g_n16);
    cudaGetSymbolAddress((void**)&w16_p, g_w16);

    const int gemm_smem = 3 * GS_STAGE;   // 147456
    cudaFuncSetAttribute(gemm_mma, cudaFuncAttributeMaxDynamicSharedMemorySize, gemm_smem);
    cudaFuncSetAttribute(gemm_f16_1t, cudaFuncAttributeMaxDynamicSharedMemorySize, gemm_smem);

    // K0a: fc_W -> single fp16
    conv_h1<<<2048, 256>>>(fc_W, w16_p, (unsigned)(VV * HH / 4));
    // K0b: W_ih -> bf16 hi/lo
    conv_split<<<256, 256>>>(W_ih, ihhi_p, ihlo_p, (unsigned)(GG * EE / 4));
    // K0c: gathered embedding -> bf16 hi/lo
    conv_emb<<<SS * BB, 128>>>(emb, x);

    // K1: input-side gate GEMM (bf16 3-term) -> g_xg
    {
        dim3 grid((SS * BB) / 128, GG / 256);  // (16, 8)
        gemm_mma<<<grid, 256, gemm_smem>>>(ahi_p, alo_p, ihhi_p, ihlo_p,
                                           b_ih, b_hh, xg_p, GG);
    }

    // K2: persistent LSTM recurrence (R9)
    {
        const int smem = (16 * HPAD * 2 + 4096 + 256 + 64) * 4;
        cudaFuncSetAttribute(lstm_kernel, cudaFuncAttributeMaxDynamicSharedMemorySize, smem);
        lstm_kernel<<<128, 256, smem>>>(W_hh, z, out + (size_t)BB * SS * VV);
    }

    // K3: layernorm -> fp16
    ln_kernel<<<BB * SS, 128>>>(ln_g, ln_b);

    // K4: FC logits GEMM (fp16 1-term)
    {
        dim3 grid((SS * BB) / 128, VV / 256);  // (16, 125)
        gemm_f16_1t<<<grid, 256, gemm_smem>>>(n16_p, w16_p, fc_b, out, VV);
    }
}

// round 16
// speedup vs baseline: 1.5058x; 1.1503x over previous
#include <cuda_runtime.h>
#include <cuda_bf16.h>
#include <cuda_fp16.h>
#include <cstdint>

// Problem constants
#define SS   128
#define BB   16
#define EE   512
#define HH   512
#define GG   2048
#define VV   32000
#define LNEPS 1e-5f

// ---------------- scratch (device globals; 256B-aligned) ----------------
__device__ __align__(256) float g_xg[SS * BB * GG];     // (s,b,g) gate preacts
__device__ __align__(256) float g_hs[BB * SS * HH];     // hidden states
__device__ __align__(256) float g_hbuf[2][BB * HH];     // ping-pong h broadcast
__device__ __align__(256) unsigned g_cnt8[2048];        // 8 counters, 1KB apart
__device__ unsigned g_master;
__device__ unsigned g_bar_gen;
// bf16 split operands (K1 path — proven)
__device__ __align__(256) __nv_bfloat16 g_ahi[SS * BB * EE];
__device__ __align__(256) __nv_bfloat16 g_alo[SS * BB * EE];
__device__ __align__(256) __nv_bfloat16 g_ihhi[GG * EE];
__device__ __align__(256) __nv_bfloat16 g_ihlo[GG * EE];
// fp16 operands (K4 path — 1-term)
__device__ __align__(256) __half g_n16[BB * SS * HH];   // LN out, single fp16
__device__ __align__(256) __half g_w16[VV * HH];        // fc_W single fp16

__device__ __forceinline__ float sigf(float x) { return 1.0f / (1.0f + __expf(-x)); }
__device__ __forceinline__ float tanhfast(float x) { return 2.0f / (1.0f + __expf(-2.0f * x)) - 1.0f; }

__device__ __forceinline__ uint32_t smem_u32(const void* p) {
    uint32_t a;
    asm("{ .reg .u64 t; cvta.to.shared.u64 t, %1; cvt.u32.u64 %0, t; }" : "=r"(a) : "l"(p));
    return a;
}

__device__ __forceinline__ void split_bf16(float v, __nv_bfloat16& h, __nv_bfloat16& l) {
    h = __float2bfloat16_rn(v);
    l = __float2bfloat16_rn(v - __bfloat162float(h));
}

__device__ __forceinline__ void ldsm_x4(uint32_t& r0, uint32_t& r1, uint32_t& r2,
                                        uint32_t& r3, uint32_t addr) {
    asm volatile("ldmatrix.sync.aligned.m8n8.x4.shared.b16 {%0,%1,%2,%3}, [%4];"
                 : "=r"(r0), "=r"(r1), "=r"(r2), "=r"(r3) : "r"(addr));
}

__device__ __forceinline__ void mma_bf16(float* c, const uint32_t* a, const uint32_t* b) {
    asm volatile(
        "mma.sync.aligned.m16n8k16.row.col.f32.bf16.bf16.f32 "
        "{%0,%1,%2,%3}, {%4,%5,%6,%7}, {%8,%9}, {%0,%1,%2,%3};"
        : "+f"(c[0]), "+f"(c[1]), "+f"(c[2]), "+f"(c[3])
        : "r"(a[0]), "r"(a[1]), "r"(a[2]), "r"(a[3]), "r"(b[0]), "r"(b[1]));
}

__device__ __forceinline__ void mma_f16(float* c, const uint32_t* a, const uint32_t* b) {
    asm volatile(
        "mma.sync.aligned.m16n8k16.row.col.f32.f16.f16.f32 "
        "{%0,%1,%2,%3}, {%4,%5,%6,%7}, {%8,%9}, {%0,%1,%2,%3};"
        : "+f"(c[0]), "+f"(c[1]), "+f"(c[2]), "+f"(c[3])
        : "r"(a[0]), "r"(a[1]), "r"(a[2]), "r"(a[3]), "r"(b[0]), "r"(b[1]));
}

// ============================================================================
// fp32 -> bf16 hi/lo split (grid-stride, float4) — K1 operands
// ============================================================================
__global__ __launch_bounds__(256) void conv_split(
    const float* __restrict__ src, __nv_bfloat16* __restrict__ dhi,
    __nv_bfloat16* __restrict__ dlo, unsigned total4)
{
    const float4* s4 = (const float4*)src;
    for (unsigned p = blockIdx.x * blockDim.x + threadIdx.x; p < total4;
         p += gridDim.x * blockDim.x) {
        float4 v = s4[p];
        __nv_bfloat16 h0, h1, h2, h3, l0, l1, l2, l3;
        split_bf16(v.x, h0, l0); split_bf16(v.y, h1, l1);
        split_bf16(v.z, h2, l2); split_bf16(v.w, h3, l3);
        ((__nv_bfloat162*)dhi)[p * 2 + 0] = __nv_bfloat162(h0, h1);
        ((__nv_bfloat162*)dhi)[p * 2 + 1] = __nv_bfloat162(h2, h3);
        ((__nv_bfloat162*)dlo)[p * 2 + 0] = __nv_bfloat162(l0, l1);
        ((__nv_bfloat162*)dlo)[p * 2 + 1] = __nv_bfloat162(l2, l3);
    }
}

// ============================================================================
// fp32 -> single fp16 (grid-stride, float4) — K4 weights
// ============================================================================
__global__ __launch_bounds__(256) void conv_h1(
    const float* __restrict__ src, __half* __restrict__ dst, unsigned total4)
{
    const float4* s4 = (const float4*)src;
    for (unsigned p = blockIdx.x * blockDim.x + threadIdx.x; p < total4;
         p += gridDim.x * blockDim.x) {
        float4 v = s4[p];
        ((__half2*)dst)[p * 2 + 0] = __half2(__float2half_rn(v.x), __float2half_rn(v.y));
        ((__half2*)dst)[p * 2 + 1] = __half2(__float2half_rn(v.z), __float2half_rn(v.w));
    }
}

// ============================================================================
// Embedding gather + bf16 hi/lo split. Row m -> token x[(m&15)*SS + (m>>4)].
// ============================================================================
__global__ __launch_bounds__(128) void conv_emb(
    const float* __restrict__ emb, const int* __restrict__ x)
{
    const int m = blockIdx.x;
    const int tid = threadIdx.x;
    const int token = x[(m & 15) * SS + (m >> 4)];
    float4 v = *(const float4*)(emb + (size_t)token * 512 + tid * 4);
    __nv_bfloat16 h0, h1, h2, h3, l0, l1, l2, l3;
    split_bf16(v.x, h0, l0); split_bf16(v.y, h1, l1);
    split_bf16(v.z, h2, l2); split_bf16(v.w, h3, l3);
    ((__nv_bfloat162*)(g_ahi + (size_t)m * 512))[tid * 2 + 0] = __nv_bfloat162(h0, h1);
    ((__nv_bfloat162*)(g_ahi + (size_t)m * 512))[tid * 2 + 1] = __nv_bfloat162(h2, h3);
    ((__nv_bfloat162*)(g_alo + (size_t)m * 512))[tid * 2 + 0] = __nv_bfloat162(l0, l1);
    ((__nv_bfloat162*)(g_alo + (size_t)m * 512))[tid * 2 + 1] = __nv_bfloat162(l2, l3);
}

// ============================================================================
// Persistent LSTM recurrence — tensor-core dot phase (bf16 3-term),
// W fragments register-resident; barrier/gate logic identical to R9.
// SMEM: [0,16K) h-hi staging, [16K,32K) h-lo, [32K,40K) red, then pre, cst.
// Staging row = 1024B (512 bf16), granule swizzle g' = g ^ (row&7).
// ============================================================================
#define LSTM_SMEM (16384 + 16384 + 8192 + 1024 + 256)

__global__ __launch_bounds__(256, 1) void lstm_kernel(
    const float* __restrict__ Whh,
    const float* __restrict__ z,
    float* __restrict__ out_hc)
{
    extern __shared__ char smc[];
    __nv_bfloat16* hsta_hi = (__nv_bfloat16*)smc;
    __nv_bfloat16* hsta_lo = (__nv_bfloat16*)(smc + 16384);
    float* red = (float*)(smc + 32768);   // 8 warps x 16 n x 16 b
    float* pre = (float*)(smc + 40960);   // 16 r x 16 b
    float* cst = (float*)(smc + 41984);   // 4 ul x 16 b
    const uint32_t sb = smem_u32(smc);

    const int tid = threadIdx.x;
    const int wid = tid >> 5;
    const int lane = tid & 31;
    const int cta = blockIdx.x;

    unsigned gen0 = 0;
    if (tid == 0) gen0 = *((volatile unsigned*)&g_bar_gen);

    // store one float2 (2 values) as bf16 hi/lo into staging row (swizzled)
    auto stage_store = [&](int row, int f2, float vx, float vy) {
        __nv_bfloat16 hx, lx, hy, ly;
        split_bf16(vx, hx, lx);
        split_bf16(vy, hy, ly);
        int g = f2 >> 2, sub = f2 & 3;
        uint32_t off = (uint32_t)(row * 1024 + ((g ^ (row & 7)) << 4) + sub * 4);
        *(__nv_bfloat162*)(smc + off)         = __nv_bfloat162(hx, hy);
        *(__nv_bfloat162*)(smc + 16384 + off) = __nv_bfloat162(lx, ly);
    };

    // --- 1) W slice -> staging (local row r -> global (r>>2)*512 + cta*4 + (r&3))
#pragma unroll
    for (int r = 0; r < 16; r++) {
        int grow = (r >> 2) * 512 + cta * 4 + (r & 3);
        float2 wv = *(const float2*)(Whh + (size_t)grow * 512 + tid * 2);
        stage_store(r, tid, wv.x, wv.y);
    }
    __syncthreads();

    // --- 2) W fragments -> registers (per-warp K slice of 64)
    const int t8 = lane >> 3, trow = lane & 7;
    const int b_fragsel = t8 >> 1, b_gsel = t8 & 1;
    const uint32_t browoff = (uint32_t)((b_fragsel * 8 + trow) * 1024);
    const uint32_t bsw = (uint32_t)((b_fragsel * 8 + trow) & 7);
    uint32_t bhi[4][2][2], blo[4][2][2];
#pragma unroll
    for (int j = 0; j < 4; j++) {
        uint32_t G = (uint32_t)((wid * 4 + j) * 2 + b_gsel);
        ldsm_x4(bhi[j][0][0], bhi[j][0][1], bhi[j][1][0], bhi[j][1][1],
                sb + browoff + ((G ^ bsw) << 4));
        ldsm_x4(blo[j][0][0], blo[j][0][1], blo[j][1][0], blo[j][1][1],
                sb + 16384u + browoff + ((G ^ bsw) << 4));
    }
    __syncthreads();   // all W frags read; repurpose staging for h

    // --- 3) h0 from z -> staging; c0 -> cst
#pragma unroll
    for (int b = 0; b < 16; b++) {
        float2 hv = *(const float2*)(z + b * 1024 + tid * 2);
        stage_store(b, tid, hv.x, hv.y);
    }
    if (tid < 64) {
        int ul = tid >> 4, b = tid & 15;
        cst[ul * 16 + b] = z[b * 1024 + 512 + cta * 4 + ul];
    }
    __syncthreads();

    // A-frag lane addressing (m16k16, rows = batches 0..15)
    const int a_mpart = (t8 & 1) * 8 + trow;
    const int a_gsel = t8 >> 1;
    const uint32_t arowoff = (uint32_t)(a_mpart * 1024);
    const uint32_t asw = (uint32_t)(a_mpart & 7);

    const int xr = tid >> 4, xb = tid & 15;
    const float* xg_addr = &g_xg[(size_t)xb * 2048 + (xr >> 2) * 512 + cta * 4 + (xr & 3)];

    for (int t = 0; t < SS; t++) {
        float xg_v = __ldg(xg_addr + (size_t)t * 16 * 2048);

        float acc0[4] = {0.f, 0.f, 0.f, 0.f};
        float acc1[4] = {0.f, 0.f, 0.f, 0.f};
#pragma unroll
        for (int j = 0; j < 4; j++) {
            uint32_t G = (uint32_t)((wid * 4 + j) * 2 + a_gsel);
            uint32_t ah[4], al[4];
            ldsm_x4(ah[0], ah[1], ah[2], ah[3],
                    sb + arowoff + ((G ^ asw) << 4));
            ldsm_x4(al[0], al[1], al[2], al[3],
                    sb + 16384u + arowoff + ((G ^ asw) << 4));
            mma_bf16(acc0, ah, bhi[j][0]); mma_bf16(acc1, ah, bhi[j][1]);
            mma_bf16(acc0, al, bhi[j][0]); mma_bf16(acc1, al, bhi[j][1]);
            mma_bf16(acc0, ah, blo[j][0]); mma_bf16(acc1, ah, blo[j][1]);
        }
        // stash partials: red[wid][n][b] (D row = batch, col = n)
        {
            int b0 = lane >> 2;
            int n0 = (lane & 3) * 2;
            float* rb = &red[wid * 256];
            rb[(n0 + 0) * 16 + b0]     = acc0[0];
            rb[(n0 + 1) * 16 + b0]     = acc0[1];
            rb[(n0 + 0) * 16 + b0 + 8] = acc0[2];
            rb[(n0 + 1) * 16 + b0 + 8] = acc0[3];
            rb[(n0 + 8) * 16 + b0]     = acc1[0];
            rb[(n0 + 9) * 16 + b0]     = acc1[1];
            rb[(n0 + 8) * 16 + b0 + 8] = acc1[2];
            rb[(n0 + 9) * 16 + b0 + 8] = acc1[3];
        }
        __syncthreads();

        {
            float s = 0.0f;
#pragma unroll
            for (int w = 0; w < 8; w++) s += red[w * 256 + xr * 16 + xb];
            pre[xr * 16 + xb] = s + xg_v;
        }
        __syncthreads();

        if (tid < 64) {
            int ul = tid >> 4, b = tid & 15;
            int ug = cta * 4 + ul;
            float iv = pre[(0  + ul) * 16 + b];
            float fv = pre[(4  + ul) * 16 + b];
            float gv = pre[(8  + ul) * 16 + b];
            float ov = pre[(12 + ul) * 16 + b];
            float c = cst[ul * 16 + b];
            c = sigf(fv) * c + sigf(iv) * tanhfast(gv);
            float hN = sigf(ov) * tanhfast(c);
            cst[ul * 16 + b] = c;
            g_hbuf[t & 1][b * 512 + ug] = hN;
            g_hs[(size_t)b * (SS * HH) + t * 512 + ug] = hN;
            if (t == SS - 1) {
                out_hc[b * 1024 + ug] = hN;
                out_hc[b * 1024 + 512 + ug] = c;
            }
        }

        if (t < SS - 1) {
            __threadfence();
            __syncthreads();
            if (tid == 0) {
                unsigned target = gen0 + (unsigned)t + 1u;
                unsigned a = atomicAdd(&g_cnt8[(cta & 7) << 8], 1u);
                if (a == 15u) {
                    unsigned m = atomicAdd(&g_master, 1u);
                    if (m == 7u) {
#pragma unroll
                        for (int q = 0; q < 8; q++)
                            atomicExch(&g_cnt8[q << 8], 0u);
                        atomicExch(&g_master, 0u);
                        __threadfence();
                        atomicAdd(&g_bar_gen, 1u);
                    }
                }
                while ((int)(*((volatile unsigned*)&g_bar_gen) - target) < 0) { }
            }
            __syncthreads();
            // reload h from L2 + convert to bf16 hi/lo staging
            const float2* src = (const float2*)(&g_hbuf[t & 1][0]);
#pragma unroll
            for (int b = 0; b < 16; b++) {
                float2 v = __ldcg(src + b * 256 + tid);
                stage_store(b, tid, v.x, v.y);
            }
            __syncthreads();
        }
    }
}

// ============================================================================
// LayerNorm -> single fp16 output
// ============================================================================
__global__ __launch_bounds__(128) void ln_kernel(
    const float* __restrict__ gamma, const float* __restrict__ beta)
{
    __shared__ float rs[4], rs2[4];
    const int m = blockIdx.x;
    const int tid = threadIdx.x;
    const float* row = g_hs + (size_t)m * 512;

    float4 v = *(const float4*)(row + tid * 4);
    float s  = v.x + v.y + v.z + v.w;
    float s2 = v.x * v.x + v.y * v.y + v.z * v.z + v.w * v.w;

    const int lane = tid & 31, w = tid >> 5;
#pragma unroll
    for (int o = 16; o; o >>= 1) {
        s  += __shfl_xor_sync(0xffffffffu, s, o);
        s2 += __shfl_xor_sync(0xffffffffu, s2, o);
    }
    if (lane == 0) { rs[w] = s; rs2[w] = s2; }
    __syncthreads();
    s  = rs[0] + rs[1] + rs[2] + rs[3];
    s2 = rs2[0] + rs2[1] + rs2[2] + rs2[3];

    float mu = s * (1.0f / 512.0f);
    float var = s2 * (1.0f / 512.0f) - mu * mu;
    float inv = rsqrtf(var + LNEPS);

    float4 g4 = *(const float4*)(gamma + tid * 4);
    float4 b4 = *(const float4*)(beta + tid * 4);
    float o0 = (v.x - mu) * inv * g4.x + b4.x;
    float o1 = (v.y - mu) * inv * g4.y + b4.y;
    float o2 = (v.z - mu) * inv * g4.z + b4.z;
    float o3 = (v.w - mu) * inv * g4.w + b4.w;

    __half2* np = (__half2*)(g_n16 + (size_t)m * 512);
    np[tid * 2 + 0] = __half2(__float2half_rn(o0), __float2half_rn(o1));
    np[tid * 2 + 1] = __half2(__float2half_rn(o2), __float2half_rn(o3));
}

// ============================================================================
// GEMM config
// ============================================================================
#define GS_STAGE 49152
#define FC_NCHUNK 16

// ============================================================================
// K1: bf16 3-term GEMM — exact R9 config (proven). C = A@B^T + bias0 + bias1
// ============================================================================
__global__ __launch_bounds__(256, 1) void gemm_mma(
    const __nv_bfloat16* __restrict__ Ahi, const __nv_bfloat16* __restrict__ Alo,
    const __nv_bfloat16* __restrict__ Bhi, const __nv_bfloat16* __restrict__ Blo,
    const float* __restrict__ bias0, const float* __restrict__ bias1,
    float* __restrict__ C, int N)
{
    extern __shared__ char smem[];
    const uint32_t sb = smem_u32(smem);
    const int tid = threadIdx.x;
    const int wid = tid >> 5;
    const int lane = tid & 31;
    const int m0 = blockIdx.x * 128;
    const int n0 = blockIdx.y * 256;
    const int warp_m = wid >> 2;
    const int warp_n = wid & 3;

    auto load_chunk = [&](int c) {
        const int k0 = c * 32;
        const uint32_t st = sb + (uint32_t)(c % 3) * GS_STAGE;
#pragma unroll
        for (int it = 0; it < 12; it++) {
            int i = it * 256 + tid;
            if (i < 1024) {
                int row = i >> 3;
                int g = i & 7;
                int part = g >> 2;
                int kg = g & 3;
                const __nv_bfloat16* src =
                    (part ? Alo : Ahi) + (size_t)(m0 + row) * 512 + k0 + kg * 8;
                uint32_t dst = st + (uint32_t)(row * 128) +
                               ((uint32_t)(g ^ (row & 7)) << 4);
                asm volatile("cp.async.cg.shared.global [%0], [%1], 16;" :: "r"(dst), "l"(src));
            } else {
                int li = i - 1024;
                int row = li >> 3;
                int g = li & 7;
                int part = g >> 2;
                int kg = g & 3;
                const __nv_bfloat16* src =
                    (part ? Blo : Bhi) + (size_t)(n0 + row) * 512 + k0 + kg * 8;
                uint32_t dst = st + 16384u + (uint32_t)(row * 128) +
                               ((uint32_t)(g ^ (row & 7)) << 4);
                asm volatile("cp.async.cg.shared.global [%0], [%1], 16;" :: "r"(dst), "l"(src));
            }
        }
        asm volatile("cp.async.commit_group;" ::: "memory");
    };

    load_chunk(0);
    load_chunk(1);

    const int t = lane >> 3, trow = lane & 7;
    const int a_mpart = (t & 1) * 8 + trow;
    const int a_gsel = t >> 1;
    uint32_t a_row_off[4]; uint32_t a_sw[4];
#pragma unroll
    for (int mf = 0; mf < 4; mf++) {
        int ml = warp_m * 64 + mf * 16 + a_mpart;
        a_row_off[mf] = (uint32_t)(ml * 128);
        a_sw[mf] = (uint32_t)(ml & 7);
    }
    const int b_fragsel = t >> 1;
    const int b_gsel = t & 1;
    uint32_t b_row_off[4]; uint32_t b_sw[4];
#pragma unroll
    for (int nf2 = 0; nf2 < 4; nf2++) {
        int nl = warp_n * 64 + (nf2 * 2 + b_fragsel) * 8 + trow;
        b_row_off[nf2] = (uint32_t)(nl * 128) + 16384u;
        b_sw[nf2] = (uint32_t)(nl & 7);
    }

    float acc[4][8][4];
#pragma unroll
    for (int i = 0; i < 4; i++)
#pragma unroll
        for (int j = 0; j < 8; j++)
#pragma unroll
            for (int r = 0; r < 4; r++) acc[i][j][r] = 0.0f;

    for (int c = 0; c < FC_NCHUNK; c++) {
        if (c < FC_NCHUNK - 1)
            asm volatile("cp.async.wait_group 1;" ::: "memory");
        else
            asm volatile("cp.async.wait_group 0;" ::: "memory");
        __syncthreads();
        if (c + 2 < FC_NCHUNK) load_chunk(c + 2);

        const uint32_t st = sb + (uint32_t)(c % 3) * GS_STAGE;
#pragma unroll
        for (int ks = 0; ks < 2; ks++) {
            uint32_t ah[4][4], al[4][4];
#pragma unroll
            for (int mf = 0; mf < 4; mf++) {
                uint32_t Ghi = (uint32_t)(ks * 2 + a_gsel);
                uint32_t Glo = Ghi + 4u;
                ldsm_x4(ah[mf][0], ah[mf][1], ah[mf][2], ah[mf][3],
                        st + a_row_off[mf] + ((Ghi ^ a_sw[mf]) << 4));
                ldsm_x4(al[mf][0], al[mf][1], al[mf][2], al[mf][3],
                        st + a_row_off[mf] + ((Glo ^ a_sw[mf]) << 4));
            }
#pragma unroll
            for (int nf2 = 0; nf2 < 4; nf2++) {
                uint32_t bh[2][2], bl[2][2];
                uint32_t Ghi = (uint32_t)(ks * 2 + b_gsel);
                uint32_t Glo = Ghi + 4u;
                ldsm_x4(bh[0][0], bh[0][1], bh[1][0], bh[1][1],
                        st + b_row_off[nf2] + ((Ghi ^ b_sw[nf2]) << 4));
                ldsm_x4(bl[0][0], bl[0][1], bl[1][0], bl[1][1],
                        st + b_row_off[nf2] + ((Glo ^ b_sw[nf2]) << 4));
#pragma unroll
                for (int mf = 0; mf < 4; mf++)
#pragma unroll
                    for (int j = 0; j < 2; j++)
                        mma_bf16(acc[mf][nf2 * 2 + j], ah[mf], bh[j]);
#pragma unroll
                for (int mf = 0; mf < 4; mf++)
#pragma unroll
                    for (int j = 0; j < 2; j++)
                        mma_bf16(acc[mf][nf2 * 2 + j], al[mf], bh[j]);
#pragma unroll
                for (int mf = 0; mf < 4; mf++)
#pragma unroll
                    for (int j = 0; j < 2; j++)
                        mma_bf16(acc[mf][nf2 * 2 + j], ah[mf], bl[j]);
            }
        }
    }

    const int lrow = lane >> 2;
    const int lcol = (lane & 3) * 2;
#pragma unroll
    for (int mf = 0; mf < 4; mf++) {
        int r0 = m0 + warp_m * 64 + mf * 16 + lrow;
        float* crow0 = C + (size_t)r0 * N;
        float* crow1 = crow0 + (size_t)8 * N;
#pragma unroll
        for (int nf = 0; nf < 8; nf++) {
            int cn = n0 + warp_n * 64 + nf * 8 + lcol;
            float b0 = __ldg(bias0 + cn);
            float b1 = __ldg(bias0 + cn + 1);
            if (bias1) { b0 += __ldg(bias1 + cn); b1 += __ldg(bias1 + cn + 1); }
            float2 v0 = { acc[mf][nf][0] + b0, acc[mf][nf][1] + b1 };
            float2 v1 = { acc[mf][nf][2] + b0, acc[mf][nf][3] + b1 };
            *(float2*)(crow0 + cn) = v0;
            *(float2*)(crow1 + cn) = v1;
        }
    }
}

// ============================================================================
// K4: fp16 1-term GEMM. A and B single fp16. C = A@B^T + bias. (proven R15)
// ============================================================================
__global__ __launch_bounds__(256, 1) void gemm_f16_1t(
    const __half* __restrict__ A16, const __half* __restrict__ B16,
    const float* __restrict__ bias0, float* __restrict__ C, int N)
{
    extern __shared__ char smem[];
    const uint32_t sb = smem_u32(smem);
    const int tid = threadIdx.x;
    const int wid = tid >> 5;
    const int lane = tid & 31;
    const int m0 = blockIdx.x * 128;
    const int n0 = blockIdx.y * 256;
    const int warp_m = wid >> 2;
    const int warp_n = wid & 3;

    auto load_chunk = [&](int c) {
        const int k0 = c * 32;
        const uint32_t st = sb + (uint32_t)(c % 3) * GS_STAGE;
#pragma unroll
        for (int it = 0; it < 6; it++) {
            int i = it * 256 + tid;
            if (i < 512) {
                int row = i >> 2;
                int g = i & 3;
                const __half* src = A16 + (size_t)(m0 + row) * 512 + k0 + g * 8;
                uint32_t dst = st + (uint32_t)(row * 128) +
                               ((uint32_t)(g ^ (row & 7)) << 4);
                asm volatile("cp.async.cg.shared.global [%0], [%1], 16;" :: "r"(dst), "l"(src));
            } else {
                int li = i - 512;
                int row = li >> 2;
                int g = li & 3;
                const __half* src = B16 + (size_t)(n0 + row) * 512 + k0 + g * 8;
                uint32_t dst = st + 16384u + (uint32_t)(row * 128) +
                               ((uint32_t)(g ^ (row & 7)) << 4);
                asm volatile("cp.async.cg.shared.global [%0], [%1], 16;" :: "r"(dst), "l"(src));
            }
        }
        asm volatile("cp.async.commit_group;" ::: "memory");
    };

    load_chunk(0);
    load_chunk(1);

    const int t = lane >> 3, trow = lane & 7;
    const int a_mpart = (t & 1) * 8 + trow;
    const int a_gsel = t >> 1;
    uint32_t a_row_off[4]; uint32_t a_sw[4];
#pragma unroll
    for (int mf = 0; mf < 4; mf++) {
        int ml = warp_m * 64 + mf * 16 + a_mpart;
        a_row_off[mf] = (uint32_t)(ml * 128);
        a_sw[mf] = (uint32_t)(ml & 7);
    }
    const int b_fragsel = t >> 1;
    const int b_gsel = t & 1;
    uint32_t b_row_off[4]; uint32_t b_sw[4];
#pragma unroll
    for (int nf2 = 0; nf2 < 4; nf2++) {
        int nl = warp_n * 64 + (nf2 * 2 + b_fragsel) * 8 + trow;
        b_row_off[nf2] = (uint32_t)(nl * 128) + 16384u;
        b_sw[nf2] = (uint32_t)(nl & 7);
    }

    float acc[4][8][4];
#pragma unroll
    for (int i = 0; i < 4; i++)
#pragma unroll
        for (int j = 0; j < 8; j++)
#pragma unroll
            for (int r = 0; r < 4; r++) acc[i][j][r] = 0.0f;

    for (int c = 0; c < FC_NCHUNK; c++) {
        if (c < FC_NCHUNK - 1)
            asm volatile("cp.async.wait_group 1;" ::: "memory");
        else
            asm volatile("cp.async.wait_group 0;" ::: "memory");
        __syncthreads();
        if (c + 2 < FC_NCHUNK) load_chunk(c + 2);

        const uint32_t st = sb + (uint32_t)(c % 3) * GS_STAGE;
#pragma unroll
        for (int ks = 0; ks < 2; ks++) {
            uint32_t ah[4][4];
#pragma unroll
            for (int mf = 0; mf < 4; mf++) {
                uint32_t Ghi = (uint32_t)(ks * 2 + a_gsel);
                ldsm_x4(ah[mf][0], ah[mf][1], ah[mf][2], ah[mf][3],
                        st + a_row_off[mf] + ((Ghi ^ a_sw[mf]) << 4));
            }
#pragma unroll
            for (int nf2 = 0; nf2 < 4; nf2++) {
                uint32_t bh[2][2];
                uint32_t Ghi = (uint32_t)(ks * 2 + b_gsel);
                ldsm_x4(bh[0][0], bh[0][1], bh[1][0], bh[1][1],
                        st + b_row_off[nf2] + ((Ghi ^ b_sw[nf2]) << 4));
#pragma unroll
                for (int mf = 0; mf < 4; mf++)
#pragma unroll
                    for (int j = 0; j < 2; j++)
                        mma_f16(acc[mf][nf2 * 2 + j], ah[mf], bh[j]);
            }
        }
    }

    const int lrow = lane >> 2;
    const int lcol = (lane & 3) * 2;
#pragma unroll
    for (int mf = 0; mf < 4; mf++) {
        int r0 = m0 + warp_m * 64 + mf * 16 + lrow;
        float* crow0 = C + (size_t)r0 * N;
        float* crow1 = crow0 + (size_t)8 * N;
#pragma unroll
        for (int nf = 0; nf < 8; nf++) {
            int cn = n0 + warp_n * 64 + nf * 8 + lcol;
            float b0 = __ldg(bias0 + cn);
            float b1 = __ldg(bias0 + cn + 1);
            float2 v0 = { acc[mf][nf][0] + b0, acc[mf][nf][1] + b1 };
            float2 v1 = { acc[mf][nf][2] + b0, acc[mf][nf][3] + b1 };
            *(float2*)(crow0 + cn) = v0;
            *(float2*)(crow1 + cn) = v1;
        }
    }
}

// ============================================================================
// launch
// ============================================================================
extern "C" void kernel_launch(void* const* d_in, const int* in_sizes, int n_in,
                              void* d_out, int out_size)
{
    const int*   x    = (const int*)d_in[0];
    const float* z    = (const float*)d_in[1];
    const float* emb  = (const float*)d_in[2];
    const float* W_ih = (const float*)d_in[3];
    const float* W_hh = (const float*)d_in[4];
    const float* b_ih = (const float*)d_in[5];
    const float* b_hh = (const float*)d_in[6];
    const float* ln_g = (const float*)d_in[7];
    const float* ln_b = (const float*)d_in[8];
    const float* fc_W = (const float*)d_in[9];
    const float* fc_b = (const float*)d_in[10];
    float* out = (float*)d_out;

    float* xg_p;
    __nv_bfloat16 *ahi_p, *alo_p, *ihhi_p, *ihlo_p;
    __half *n16_p, *w16_p;
    cudaGetSymbolAddress((void**)&xg_p, g_xg);
    cudaGetSymbolAddress((void**)&ahi_p, g_ahi);
    cudaGetSymbolAddress((void**)&alo_p, g_alo);
    cudaGetSymbolAddress((void**)&ihhi_p, g_ihhi);
    cudaGetSymbolAddress((void**)&ihlo_p, g_ihlo);
    cudaGetSymbolAddress((void**)&n16_p, g_n16);
    cudaGetSymbolAddress((void**)&w16_p, g_w16);

    const int gemm_smem = 3 * GS_STAGE;   // 147456
    cudaFuncSetAttribute(gemm_mma, cudaFuncAttributeMaxDynamicSharedMemorySize, gemm_smem);
    cudaFuncSetAttribute(gemm_f16_1t, cudaFuncAttributeMaxDynamicSharedMemorySize, gemm_smem);

    // K0a: fc_W -> single fp16
    conv_h1<<<2048, 256>>>(fc_W, w16_p, (unsigned)(VV * HH / 4));
    // K0b: W_ih -> bf16 hi/lo
    conv_split<<<256, 256>>>(W_ih, ihhi_p, ihlo_p, (unsigned)(GG * EE / 4));
    // K0c: gathered embedding -> bf16 hi/lo
    conv_emb<<<SS * BB, 128>>>(emb, x);

    // K1: input-side gate GEMM (bf16 3-term) -> g_xg
    {
        dim3 grid((SS * BB) / 128, GG / 256);  // (16, 8)
        gemm_mma<<<grid, 256, gemm_smem>>>(ahi_p, alo_p, ihhi_p, ihlo_p,
                                           b_ih, b_hh, xg_p, GG);
    }

    // K2: persistent LSTM recurrence (tensor-core dot)
    {
        cudaFuncSetAttribute(lstm_kernel, cudaFuncAttributeMaxDynamicSharedMemorySize,
                             LSTM_SMEM);
        lstm_kernel<<<128, 256, LSTM_SMEM>>>(W_hh, z, out + (size_t)BB * SS * VV);
    }

    // K3: layernorm -> fp16
    ln_kernel<<<BB * SS, 128>>>(ln_g, ln_b);

    // K4: FC logits GEMM (fp16 1-term)
    {
        dim3 grid((SS * BB) / 128, VV / 256);  // (16, 125)
        gemm_f16_1t<<<grid, 256, gemm_smem>>>(n16_p, w16_p, fc_b, out, VV);
    }
}